// round 7
// baseline (speedup 1.0000x reference)
#include <cuda_runtime.h>
#include <cuda_fp8.h>

// Problem: B=8192, C = N*D = 2048, K = 1024
#define C_DIM 2048
#define K_DIM 1024
#define B_MAX 8192

// ---------------- device scratch ----------------
__device__ unsigned char g_zb[(size_t)B_MAX * C_DIM];   // 16 MB fp8
__device__ unsigned char g_wb[(size_t)K_DIM * C_DIM];   // 2 MB fp8
__device__ float g_scores[(size_t)B_MAX * K_DIM];       // 32 MB
__device__ float g_whalf[K_DIM];
__device__ float g_loss;

// ---------------- prep_w: fp32->fp8 convert + 0.5*||w||^2 + zero loss ----------------
__global__ __launch_bounds__(256) void prep_w_k(const float* __restrict__ w,
                                                unsigned char* __restrict__ wb)
{
    const int k = blockIdx.x;
    const int t = threadIdx.x;
    if (k == 0 && t == 0) g_loss = 0.0f;

    const float4* wr = (const float4*)(w + (size_t)k * C_DIM);
    float4 a = wr[t * 2];
    float4 b = wr[t * 2 + 1];

    uint2 u;
    u.x = __nv_fp8x4_e4m3(a).__x;
    u.y = __nv_fp8x4_e4m3(b).__x;
    ((uint2*)(wb + (size_t)k * C_DIM))[t] = u;

    float s = a.x * a.x + a.y * a.y + a.z * a.z + a.w * a.w
            + b.x * b.x + b.y * b.y + b.z * b.z + b.w * b.w;
    __shared__ float red[256];
    red[t] = s;
    __syncthreads();
    for (int o = 128; o > 0; o >>= 1) {
        if (t < o) red[t] += red[t + o];
        __syncthreads();
    }
    if (t == 0) g_whalf[k] = 0.5f * red[0];
}

// ---------------- cvt_z: fp32 -> fp8 ----------------
__global__ void cvt_z_k(const float* __restrict__ src, unsigned char* __restrict__ dst, int n16) {
    int i = blockIdx.x * blockDim.x + threadIdx.x;
    int stride = gridDim.x * blockDim.x;
    const float4* s4 = (const float4*)src;
    for (; i < n16; i += stride) {
        uint4 u;
        u.x = __nv_fp8x4_e4m3(s4[i * 4 + 0]).__x;
        u.y = __nv_fp8x4_e4m3(s4[i * 4 + 1]).__x;
        u.z = __nv_fp8x4_e4m3(s4[i * 4 + 2]).__x;
        u.w = __nv_fp8x4_e4m3(s4[i * 4 + 3]).__x;
        ((uint4*)dst)[i] = u;
    }
}

// ---------------- fp8 mma.sync GEMM: scores = zb . wb^T ----------------
// BM=128, BN=128, BK=128 fp8 elems (128 B), 3-stage cp.async, 8 warps (32x64 warp tile).
#define BM 128
#define BN 128
#define BKB 128           // K-chunk bytes per stage (= 128 fp8 elems)
#define STAGES 3
#define A_ST (BM * BKB)   // 16384 B
#define B_ST (BN * BKB)   // 16384 B
#define GSMEM (STAGES * (A_ST + B_ST) + 1024)
#define NITER (C_DIM / BKB)   // 16

#define SWZ128(off) ((off) ^ (((off) >> 3) & 0x70))

__device__ __forceinline__ unsigned smem_u32(const void* p) {
    unsigned a;
    asm("{ .reg .u64 t; cvta.to.shared.u64 t, %1; cvt.u32.u64 %0, t; }" : "=r"(a) : "l"(p));
    return a;
}
__device__ __forceinline__ void cp16(unsigned s, const void* g) {
    asm volatile("cp.async.cg.shared.global [%0], [%1], 16;" :: "r"(s), "l"(g));
}
__device__ __forceinline__ void ldm4(unsigned* d, unsigned addr) {
    asm volatile("ldmatrix.sync.aligned.m8n8.x4.shared.b16 {%0,%1,%2,%3}, [%4];"
                 : "=r"(d[0]), "=r"(d[1]), "=r"(d[2]), "=r"(d[3]) : "r"(addr));
}
__device__ __forceinline__ void mma_fp8(float* c, const unsigned* a, unsigned b0, unsigned b1) {
    asm volatile(
        "mma.sync.aligned.m16n8k32.row.col.f32.e4m3.e4m3.f32 "
        "{%0,%1,%2,%3}, {%4,%5,%6,%7}, {%8,%9}, {%0,%1,%2,%3};"
        : "+f"(c[0]), "+f"(c[1]), "+f"(c[2]), "+f"(c[3])
        : "r"(a[0]), "r"(a[1]), "r"(a[2]), "r"(a[3]), "r"(b0), "r"(b1));
}

__global__ __launch_bounds__(256, 2) void gemm_k(
    const unsigned char* __restrict__ zb,
    const unsigned char* __restrict__ wb,
    float* __restrict__ scores)
{
    extern __shared__ char dsm[];
    unsigned base = (smem_u32(dsm) + 1023u) & ~1023u;
    const unsigned aB = base;
    const unsigned bB = base + STAGES * A_ST;

    const int tid = threadIdx.x;
    const int wid = tid >> 5;
    const int lane = tid & 31;
    const int wm = wid & 3;       // warp rows: wm*32
    const int wn = wid >> 2;      // warp cols: wn*64

    const unsigned char* zrow = zb + (size_t)(blockIdx.x * BM) * C_DIM;
    const unsigned char* wrow = wb + (size_t)(blockIdx.y * BN) * C_DIM;

    const int lr = tid >> 3;          // 0..31 (row within 32-row group)
    const int lc = (tid & 7) * 16;    // byte col 0..112

    float acc[2][8][4];
#pragma unroll
    for (int i = 0; i < 2; i++)
#pragma unroll
        for (int j = 0; j < 8; j++)
#pragma unroll
            for (int q = 0; q < 4; q++) acc[i][j][q] = 0.0f;

    // prefetch stages 0..STAGES-2
#pragma unroll
    for (int s = 0; s < STAGES - 1; s++) {
        int kb = s * BKB;
#pragma unroll
        for (int r = 0; r < 4; r++) {
            int row = r * 32 + lr;
            cp16(aB + s * A_ST + SWZ128((unsigned)(row * BKB + lc)),
                 zrow + (size_t)row * C_DIM + kb + lc);
            cp16(bB + s * B_ST + SWZ128((unsigned)(row * BKB + lc)),
                 wrow + (size_t)row * C_DIM + kb + lc);
        }
        asm volatile("cp.async.commit_group;");
    }

    for (int i = 0; i < NITER; i++) {
        asm volatile("cp.async.wait_group %0;" :: "n"(STAGES - 2));
        __syncthreads();

        if (i + STAGES - 1 < NITER) {
            int s = (i + STAGES - 1) % STAGES;
            int kb = (i + STAGES - 1) * BKB;
#pragma unroll
            for (int r = 0; r < 4; r++) {
                int row = r * 32 + lr;
                cp16(aB + s * A_ST + SWZ128((unsigned)(row * BKB + lc)),
                     zrow + (size_t)row * C_DIM + kb + lc);
                cp16(bB + s * B_ST + SWZ128((unsigned)(row * BKB + lc)),
                     wrow + (size_t)row * C_DIM + kb + lc);
            }
        }
        asm volatile("cp.async.commit_group;");

        const unsigned aS = aB + (i % STAGES) * A_ST;
        const unsigned bS = bB + (i % STAGES) * B_ST;
        const int lrow = lane & 15;
        const int lhalf = (lane >> 4) * 16;   // 16B half within a 32B k-chunk

#pragma unroll
        for (int kk = 0; kk < 4; kk++) {       // 4 x k32 (32 B) per 128 B chunk
            const int kbyte = kk * 32;
            unsigned af[2][4];
#pragma unroll
            for (int mt = 0; mt < 2; mt++) {
                int row = wm * 32 + mt * 16 + lrow;
                ldm4(af[mt], aS + SWZ128((unsigned)(row * BKB + kbyte + lhalf)));
            }
            unsigned bf[4][4];
#pragma unroll
            for (int nt2 = 0; nt2 < 4; nt2++) {
                int row = wn * 64 + nt2 * 16 + lrow;
                ldm4(bf[nt2], bS + SWZ128((unsigned)(row * BKB + kbyte + lhalf)));
            }
#pragma unroll
            for (int mt = 0; mt < 2; mt++)
#pragma unroll
                for (int nt = 0; nt < 8; nt++) {
                    const unsigned* bv = bf[nt >> 1];
                    unsigned b0 = (nt & 1) ? bv[1] : bv[0];
                    unsigned b1 = (nt & 1) ? bv[3] : bv[2];
                    mma_fp8(acc[mt][nt], af[mt], b0, b1);
                }
        }
    }

    const int r0 = blockIdx.x * BM + wm * 32 + (lane >> 2);
    const int c0 = blockIdx.y * BN + wn * 64 + (lane & 3) * 2;
#pragma unroll
    for (int mt = 0; mt < 2; mt++) {
#pragma unroll
        for (int nt = 0; nt < 8; nt++) {
            float* p = scores + (size_t)(r0 + mt * 16) * K_DIM + c0 + nt * 8;
            *(float2*)p = make_float2(acc[mt][nt][0], acc[mt][nt][1]);
            *(float2*)(p + 8 * K_DIM) = make_float2(acc[mt][nt][2], acc[mt][nt][3]);
        }
    }
}

// ---------------- fused select (approx argmax + exact refine) + gather + loss ----------------
#define MARGIN 24.0f
#define MAXC 65   // slot 0 = approx best

__global__ __launch_bounds__(256) void selgather_k(const float* __restrict__ z,
                                                   const float* __restrict__ w,
                                                   float* __restrict__ out)
{
    const int b = blockIdx.x;
    const int t = threadIdx.x;
    const int lane = t & 31;
    const int wp = t >> 5;

    __shared__ float s_wv[8];
    __shared__ int   s_wi[8];
    __shared__ float s_best;
    __shared__ int   s_besti;
    __shared__ int   s_cnt;
    __shared__ int   s_cand[MAXC];
    __shared__ float s_res[MAXC];
    __shared__ int   s_ind;
    __shared__ float s_red[8];

    // scores for this row: 4 per thread
    float4 sc = ((const float4*)(g_scores + (size_t)b * K_DIM))[t];
    float4 wh = ((const float4*)g_whalf)[t];
    float v[4] = { sc.x - wh.x, sc.y - wh.y, sc.z - wh.z, sc.w - wh.w };

    float bv = v[0];
    int bi = 4 * t;
#pragma unroll
    for (int j = 1; j < 4; j++)
        if (v[j] > bv) { bv = v[j]; bi = 4 * t + j; }

    for (int o = 16; o > 0; o >>= 1) {
        float ov = __shfl_down_sync(0xFFFFFFFFu, bv, o);
        int   oi = __shfl_down_sync(0xFFFFFFFFu, bi, o);
        if (ov > bv || (ov == bv && oi < bi)) { bv = ov; bi = oi; }
    }
    if (lane == 0) { s_wv[wp] = bv; s_wi[wp] = bi; }
    if (t == 0) s_cnt = 0;
    __syncthreads();
    if (t == 0) {
        float gb = s_wv[0]; int gi = s_wi[0];
        for (int i2 = 1; i2 < 8; i2++) {
            float ov = s_wv[i2]; int oi = s_wi[i2];
            if (ov > gb || (ov == gb && oi < gi)) { gb = ov; gi = oi; }
        }
        s_best = gb; s_besti = gi; s_cand[0] = gi;
    }
    __syncthreads();
    const float gbest = s_best;
    const int gbesti = s_besti;
    const float th = gbest - MARGIN;

#pragma unroll
    for (int j = 0; j < 4; j++) {
        int k = 4 * t + j;
        if (v[j] >= th && k != gbesti) {
            int p = atomicAdd(&s_cnt, 1);
            if (p < MAXC - 1) s_cand[p + 1] = k;
        }
    }
    __syncthreads();
    int nc = s_cnt < (MAXC - 1) ? s_cnt : (MAXC - 1);

    int ind;
    if (nc == 0) {
        ind = gbesti;
    } else {
        const int total = nc + 1;
        const float4* zr4 = (const float4*)(z + (size_t)b * C_DIM);
        // one candidate per warp, exact fp32 dot
        for (int ci = wp; ci < total; ci += 8) {
            int k = s_cand[ci];
            const float4* wr4 = (const float4*)(w + (size_t)k * C_DIM);
            float p = 0.0f;
#pragma unroll
            for (int d = 0; d < 16; d++) {
                float4 zv = zr4[lane + d * 32];
                float4 wv = wr4[lane + d * 32];
                p += zv.x * wv.x + zv.y * wv.y + zv.z * wv.z + zv.w * wv.w;
            }
            for (int o = 16; o > 0; o >>= 1) p += __shfl_down_sync(0xFFFFFFFFu, p, o);
            if (lane == 0) s_res[ci] = p - g_whalf[k];
        }
        __syncthreads();
        if (t == 0) {
            float ebv = -3.4e38f; int ebi = 0;
            for (int ci = 0; ci < total; ci++) {
                int k = s_cand[ci];
                float s = s_res[ci];
                if (s > ebv || (s == ebv && k < ebi)) { ebv = s; ebi = k; }
            }
            s_ind = ebi;
        }
        __syncthreads();
        ind = s_ind;
    }

    // gather z_q = w[ind], exact loss accumulation
    const float4* wr = (const float4*)(w + (size_t)ind * C_DIM);
    const float4* zr = (const float4*)(z + (size_t)b * C_DIM);
    float4* o4 = (float4*)(out + (size_t)b * C_DIM);
    float sacc = 0.0f;
#pragma unroll
    for (int c = t; c < C_DIM / 4; c += 256) {
        float4 wv = wr[c];
        float4 zv = zr[c];
        o4[c] = wv;
        float d0 = wv.x - zv.x, d1 = wv.y - zv.y, d2 = wv.z - zv.z, d3 = wv.w - zv.w;
        sacc += d0 * d0 + d1 * d1 + d2 * d2 + d3 * d3;
    }
    for (int o = 16; o > 0; o >>= 1) sacc += __shfl_down_sync(0xFFFFFFFFu, sacc, o);
    if (lane == 0) s_red[wp] = sacc;
    __syncthreads();
    if (t == 0) {
        float tot = 0.0f;
        for (int i2 = 0; i2 < 8; i2++) tot += s_red[i2];
        atomicAdd(&g_loss, tot);
    }
}

__global__ void fin_k(float* out, int loss_idx, float inv_n) {
    out[loss_idx] = 12.5f * g_loss * inv_n;   // KLD_SCALE*(1+COMMITMENT_COST)*mse
}

extern "C" void kernel_launch(void* const* d_in, const int* in_sizes, int n_in,
                              void* d_out, int out_size)
{
    const float* z = (const float*)d_in[0];
    const float* w = (const float*)d_in[1];
    float* out = (float*)d_out;
    const int B = in_sizes[0] / C_DIM;   // 8192

    void* p_zb; cudaGetSymbolAddress(&p_zb, g_zb);
    void* p_wb; cudaGetSymbolAddress(&p_wb, g_wb);
    void* p_sc; cudaGetSymbolAddress(&p_sc, g_scores);

    cudaFuncSetAttribute(gemm_k, cudaFuncAttributeMaxDynamicSharedMemorySize, GSMEM);

    cvt_z_k<<<2048, 256>>>(z, (unsigned char*)p_zb, B * C_DIM / 16);
    prep_w_k<<<K_DIM, 256>>>(w, (unsigned char*)p_wb);

    dim3 ggrid(B / BM, K_DIM / BN);
    gemm_k<<<ggrid, 256, GSMEM>>>((const unsigned char*)p_zb,
                                  (const unsigned char*)p_wb,
                                  (float*)p_sc);

    selgather_k<<<B, 256>>>(z, w, out);
    fin_k<<<1, 1>>>(out, out_size - 1, 1.0f / ((float)B * (float)C_DIM));
}

// round 8
// speedup vs baseline: 1.5763x; 1.5763x over previous
#include <cuda_runtime.h>

// Problem: B=8192, C = N*D = 2048, K = 1024
#define C_DIM 2048
#define K_DIM 1024
#define B_MAX 8192

#define QSCALE 23.0f
#define QINV2 (1.0f / (QSCALE * QSCALE))

// ---------------- device scratch ----------------
__device__ signed char g_zb[(size_t)B_MAX * C_DIM];   // 16 MB int8
__device__ signed char g_wb[(size_t)K_DIM * C_DIM];   // 2 MB int8
__device__ float g_scores[(size_t)B_MAX * K_DIM];     // 32 MB
__device__ float g_whalf[K_DIM];
__device__ int   g_ind[B_MAX];
__device__ float g_loss;

__device__ __forceinline__ unsigned pack_s8(float4 v) {
    int a = max(-127, min(127, __float2int_rn(v.x * QSCALE)));
    int b = max(-127, min(127, __float2int_rn(v.y * QSCALE)));
    int c = max(-127, min(127, __float2int_rn(v.z * QSCALE)));
    int d = max(-127, min(127, __float2int_rn(v.w * QSCALE)));
    return (unsigned)(a & 0xff) | ((unsigned)(b & 0xff) << 8)
         | ((unsigned)(c & 0xff) << 16) | ((unsigned)(d & 0xff) << 24);
}

// ---------------- cvt_z: fp32 -> int8 ----------------
__global__ void cvt_z_k(const float* __restrict__ src, signed char* __restrict__ dst, int n16) {
    int i = blockIdx.x * blockDim.x + threadIdx.x;
    int stride = gridDim.x * blockDim.x;
    const float4* s4 = (const float4*)src;
    for (; i < n16; i += stride) {
        uint4 u;
        u.x = pack_s8(s4[i * 4 + 0]);
        u.y = pack_s8(s4[i * 4 + 1]);
        u.z = pack_s8(s4[i * 4 + 2]);
        u.w = pack_s8(s4[i * 4 + 3]);
        ((uint4*)dst)[i] = u;
    }
}

// ---------------- prep_w: fp32->int8 + 0.5*||w||^2 (exact) + zero loss ----------------
__global__ __launch_bounds__(256) void prep_w_k(const float* __restrict__ w,
                                                signed char* __restrict__ wb)
{
    const int k = blockIdx.x;
    const int t = threadIdx.x;
    if (k == 0 && t == 0) g_loss = 0.0f;

    const float4* wr = (const float4*)(w + (size_t)k * C_DIM);
    float4 a = wr[t * 2];
    float4 b = wr[t * 2 + 1];

    uint2 u;
    u.x = pack_s8(a);
    u.y = pack_s8(b);
    ((uint2*)(wb + (size_t)k * C_DIM))[t] = u;

    float s = a.x * a.x + a.y * a.y + a.z * a.z + a.w * a.w
            + b.x * b.x + b.y * b.y + b.z * b.z + b.w * b.w;
    __shared__ float red[256];
    red[t] = s;
    __syncthreads();
    for (int o = 128; o > 0; o >>= 1) {
        if (t < o) red[t] += red[t + o];
        __syncthreads();
    }
    if (t == 0) g_whalf[k] = 0.5f * red[0];
}

// ---------------- int8 mma.sync GEMM: scores = (zq . wq^T) / QSCALE^2 ----------------
#define BM 128
#define BN 128
#define BKB 128           // K-chunk bytes per stage (= 128 int8 elems)
#define STAGES 3
#define A_ST (BM * BKB)
#define B_ST (BN * BKB)
#define GSMEM (STAGES * (A_ST + B_ST) + 1024)
#define NITER (C_DIM / BKB)   // 16

#define SWZ128(off) ((off) ^ (((off) >> 3) & 0x70))

__device__ __forceinline__ unsigned smem_u32(const void* p) {
    unsigned a;
    asm("{ .reg .u64 t; cvta.to.shared.u64 t, %1; cvt.u32.u64 %0, t; }" : "=r"(a) : "l"(p));
    return a;
}
__device__ __forceinline__ void cp16(unsigned s, const void* g) {
    asm volatile("cp.async.cg.shared.global [%0], [%1], 16;" :: "r"(s), "l"(g));
}
__device__ __forceinline__ void ldm4(unsigned* d, unsigned addr) {
    asm volatile("ldmatrix.sync.aligned.m8n8.x4.shared.b16 {%0,%1,%2,%3}, [%4];"
                 : "=r"(d[0]), "=r"(d[1]), "=r"(d[2]), "=r"(d[3]) : "r"(addr));
}
__device__ __forceinline__ void mma_s8(int* c, const unsigned* a, unsigned b0, unsigned b1) {
    asm volatile(
        "mma.sync.aligned.m16n8k32.row.col.s32.s8.s8.s32 "
        "{%0,%1,%2,%3}, {%4,%5,%6,%7}, {%8,%9}, {%0,%1,%2,%3};"
        : "+r"(c[0]), "+r"(c[1]), "+r"(c[2]), "+r"(c[3])
        : "r"(a[0]), "r"(a[1]), "r"(a[2]), "r"(a[3]), "r"(b0), "r"(b1));
}

__global__ __launch_bounds__(256, 2) void gemm_k(
    const signed char* __restrict__ zb,
    const signed char* __restrict__ wb,
    float* __restrict__ scores)
{
    extern __shared__ char dsm[];
    unsigned base = (smem_u32(dsm) + 1023u) & ~1023u;
    const unsigned aB = base;
    const unsigned bB = base + STAGES * A_ST;

    const int tid = threadIdx.x;
    const int wid = tid >> 5;
    const int lane = tid & 31;
    const int wm = wid & 3;       // warp rows: wm*32
    const int wn = wid >> 2;      // warp cols: wn*64

    const signed char* zrow = zb + (size_t)(blockIdx.x * BM) * C_DIM;
    const signed char* wrow = wb + (size_t)(blockIdx.y * BN) * C_DIM;

    const int lr = tid >> 3;
    const int lc = (tid & 7) * 16;

    int acc[2][8][4];
#pragma unroll
    for (int i = 0; i < 2; i++)
#pragma unroll
        for (int j = 0; j < 8; j++)
#pragma unroll
            for (int q = 0; q < 4; q++) acc[i][j][q] = 0;

#pragma unroll
    for (int s = 0; s < STAGES - 1; s++) {
        int kb = s * BKB;
#pragma unroll
        for (int r = 0; r < 4; r++) {
            int row = r * 32 + lr;
            cp16(aB + s * A_ST + SWZ128((unsigned)(row * BKB + lc)),
                 zrow + (size_t)row * C_DIM + kb + lc);
            cp16(bB + s * B_ST + SWZ128((unsigned)(row * BKB + lc)),
                 wrow + (size_t)row * C_DIM + kb + lc);
        }
        asm volatile("cp.async.commit_group;");
    }

    for (int i = 0; i < NITER; i++) {
        asm volatile("cp.async.wait_group %0;" :: "n"(STAGES - 2));
        __syncthreads();

        if (i + STAGES - 1 < NITER) {
            int s = (i + STAGES - 1) % STAGES;
            int kb = (i + STAGES - 1) * BKB;
#pragma unroll
            for (int r = 0; r < 4; r++) {
                int row = r * 32 + lr;
                cp16(aB + s * A_ST + SWZ128((unsigned)(row * BKB + lc)),
                     zrow + (size_t)row * C_DIM + kb + lc);
                cp16(bB + s * B_ST + SWZ128((unsigned)(row * BKB + lc)),
                     wrow + (size_t)row * C_DIM + kb + lc);
            }
        }
        asm volatile("cp.async.commit_group;");

        const unsigned aS = aB + (i % STAGES) * A_ST;
        const unsigned bS = bB + (i % STAGES) * B_ST;
        const int lrow = lane & 15;
        const int lhalf = (lane >> 4) * 16;

#pragma unroll
        for (int kk = 0; kk < 4; kk++) {       // 4 x k32 (32 B) per 128 B chunk
            const int kbyte = kk * 32;
            unsigned af[2][4];
#pragma unroll
            for (int mt = 0; mt < 2; mt++) {
                int row = wm * 32 + mt * 16 + lrow;
                ldm4(af[mt], aS + SWZ128((unsigned)(row * BKB + kbyte + lhalf)));
            }
            unsigned bf[4][4];
#pragma unroll
            for (int nt2 = 0; nt2 < 4; nt2++) {
                int row = wn * 64 + nt2 * 16 + lrow;
                ldm4(bf[nt2], bS + SWZ128((unsigned)(row * BKB + kbyte + lhalf)));
            }
#pragma unroll
            for (int mt = 0; mt < 2; mt++)
#pragma unroll
                for (int nt = 0; nt < 8; nt++) {
                    const unsigned* bv = bf[nt >> 1];
                    unsigned b0 = (nt & 1) ? bv[1] : bv[0];
                    unsigned b1 = (nt & 1) ? bv[3] : bv[2];
                    mma_s8(acc[mt][nt], af[mt], b0, b1);
                }
        }
    }

    const int r0 = blockIdx.x * BM + wm * 32 + (lane >> 2);
    const int c0 = blockIdx.y * BN + wn * 64 + (lane & 3) * 2;
#pragma unroll
    for (int mt = 0; mt < 2; mt++) {
#pragma unroll
        for (int nt = 0; nt < 8; nt++) {
            float* p = scores + (size_t)(r0 + mt * 16) * K_DIM + c0 + nt * 8;
            *(float2*)p = make_float2((float)acc[mt][nt][0] * QINV2,
                                      (float)acc[mt][nt][1] * QINV2);
            *(float2*)(p + 8 * K_DIM) = make_float2((float)acc[mt][nt][2] * QINV2,
                                                    (float)acc[mt][nt][3] * QINV2);
        }
    }
}

// ---------------- select: approx argmax + exact fp32 refine ----------------
#define MARGIN 8.0f
#define MAXC 33   // slot 0 = approx best

__global__ __launch_bounds__(256) void select_k(const float* __restrict__ z,
                                                const float* __restrict__ w)
{
    const int b = blockIdx.x;
    const int t = threadIdx.x;
    const int lane = t & 31;
    const int wp = t >> 5;

    __shared__ float s_wv[8];
    __shared__ int   s_wi[8];
    __shared__ float s_best;
    __shared__ int   s_besti;
    __shared__ int   s_cnt;
    __shared__ int   s_cand[MAXC];
    __shared__ float s_res[MAXC];

    float4 sc = ((const float4*)(g_scores + (size_t)b * K_DIM))[t];
    float4 wh = ((const float4*)g_whalf)[t];
    float v[4] = { sc.x - wh.x, sc.y - wh.y, sc.z - wh.z, sc.w - wh.w };

    float bv = v[0];
    int bi = 4 * t;
#pragma unroll
    for (int j = 1; j < 4; j++)
        if (v[j] > bv) { bv = v[j]; bi = 4 * t + j; }

    for (int o = 16; o > 0; o >>= 1) {
        float ov = __shfl_down_sync(0xFFFFFFFFu, bv, o);
        int   oi = __shfl_down_sync(0xFFFFFFFFu, bi, o);
        if (ov > bv || (ov == bv && oi < bi)) { bv = ov; bi = oi; }
    }
    if (lane == 0) { s_wv[wp] = bv; s_wi[wp] = bi; }
    if (t == 0) s_cnt = 0;
    __syncthreads();
    if (t == 0) {
        float gb = s_wv[0]; int gi = s_wi[0];
        for (int i2 = 1; i2 < 8; i2++) {
            float ov = s_wv[i2]; int oi = s_wi[i2];
            if (ov > gb || (ov == gb && oi < gi)) { gb = ov; gi = oi; }
        }
        s_best = gb; s_besti = gi; s_cand[0] = gi;
    }
    __syncthreads();
    const float th = s_best - MARGIN;
    const int gbesti = s_besti;

#pragma unroll
    for (int j = 0; j < 4; j++) {
        int k = 4 * t + j;
        if (v[j] >= th && k != gbesti) {
            int p = atomicAdd(&s_cnt, 1);
            if (p < MAXC - 1) s_cand[p + 1] = k;
        }
    }
    __syncthreads();
    int nc = s_cnt < (MAXC - 1) ? s_cnt : (MAXC - 1);

    if (nc == 0) {
        if (t == 0) g_ind[b] = gbesti;
        return;
    }

    // exact fp32 dots, one candidate per warp
    const int total = nc + 1;
    const float4* zr4 = (const float4*)(z + (size_t)b * C_DIM);
    for (int ci = wp; ci < total; ci += 8) {
        int k = s_cand[ci];
        const float4* wr4 = (const float4*)(w + (size_t)k * C_DIM);
        float p = 0.0f;
#pragma unroll
        for (int d = 0; d < 16; d++) {
            float4 zv = zr4[lane + d * 32];
            float4 wv = wr4[lane + d * 32];
            p += zv.x * wv.x + zv.y * wv.y + zv.z * wv.z + zv.w * wv.w;
        }
        for (int o = 16; o > 0; o >>= 1) p += __shfl_down_sync(0xFFFFFFFFu, p, o);
        if (lane == 0) s_res[ci] = p - g_whalf[k];
    }
    __syncthreads();
    if (t == 0) {
        float ebv = -3.4e38f; int ebi = 0;
        for (int ci = 0; ci < total; ci++) {
            int k = s_cand[ci];
            float s = s_res[ci];
            if (s > ebv || (s == ebv && k < ebi)) { ebv = s; ebi = k; }
        }
        g_ind[b] = ebi;
    }
}

// ---------------- gather z_q = w[ind], exact sum((w[ind]-z)^2) ----------------
__global__ __launch_bounds__(256) void gather_k(const float* __restrict__ z,
                                                const float* __restrict__ w,
                                                float* __restrict__ out)
{
    int b = blockIdx.x;
    int ind = g_ind[b];
    const float4* wr = (const float4*)(w + (size_t)ind * C_DIM);
    const float4* zr = (const float4*)(z + (size_t)b * C_DIM);
    float4* o4 = (float4*)(out + (size_t)b * C_DIM);

    float s = 0.0f;
#pragma unroll
    for (int c = threadIdx.x; c < C_DIM / 4; c += 256) {
        float4 wv = __ldg(&wr[c]);
        float4 zv;
        asm("ld.global.cs.v4.f32 {%0,%1,%2,%3}, [%4];"
            : "=f"(zv.x), "=f"(zv.y), "=f"(zv.z), "=f"(zv.w) : "l"(zr + c));
        asm volatile("st.global.cs.v4.f32 [%0], {%1,%2,%3,%4};"
            :: "l"(o4 + c), "f"(wv.x), "f"(wv.y), "f"(wv.z), "f"(wv.w));
        float d0 = wv.x - zv.x, d1 = wv.y - zv.y, d2 = wv.z - zv.z, d3 = wv.w - zv.w;
        s += d0 * d0 + d1 * d1 + d2 * d2 + d3 * d3;
    }
    for (int o = 16; o > 0; o >>= 1) s += __shfl_down_sync(0xFFFFFFFFu, s, o);
    __shared__ float red[8];
    if ((threadIdx.x & 31) == 0) red[threadIdx.x >> 5] = s;
    __syncthreads();
    if (threadIdx.x == 0) {
        float tot = 0.0f;
        for (int i = 0; i < 8; i++) tot += red[i];
        atomicAdd(&g_loss, tot);
    }
}

__global__ void fin_k(float* out, int loss_idx, float inv_n) {
    out[loss_idx] = 12.5f * g_loss * inv_n;   // KLD_SCALE*(1+COMMITMENT_COST)*mse
}

extern "C" void kernel_launch(void* const* d_in, const int* in_sizes, int n_in,
                              void* d_out, int out_size)
{
    const float* z = (const float*)d_in[0];
    const float* w = (const float*)d_in[1];
    float* out = (float*)d_out;
    const int B = in_sizes[0] / C_DIM;   // 8192

    void* p_zb; cudaGetSymbolAddress(&p_zb, g_zb);
    void* p_wb; cudaGetSymbolAddress(&p_wb, g_wb);
    void* p_sc; cudaGetSymbolAddress(&p_sc, g_scores);

    cudaFuncSetAttribute(gemm_k, cudaFuncAttributeMaxDynamicSharedMemorySize, GSMEM);

    cvt_z_k<<<2048, 256>>>(z, (signed char*)p_zb, B * C_DIM / 16);
    prep_w_k<<<K_DIM, 256>>>(w, (signed char*)p_wb);

    dim3 ggrid(B / BM, K_DIM / BN);
    gemm_k<<<ggrid, 256, GSMEM>>>((const signed char*)p_zb,
                                  (const signed char*)p_wb,
                                  (float*)p_sc);

    select_k<<<B, 256>>>(z, w);
    gather_k<<<B, 256>>>(z, w, out);
    fin_k<<<1, 1>>>(out, out_size - 1, 1.0f / ((float)B * (float)C_DIM));
}

// round 9
// speedup vs baseline: 1.6535x; 1.0490x over previous
#include <cuda_runtime.h>

// Problem: B=8192, C = N*D = 2048, K = 1024
#define C_DIM 2048
#define K_DIM 1024
#define B_MAX 8192

#define QSCALE 23.0f
#define QINV2 (1.0f / (QSCALE * QSCALE))

// ---------------- device scratch ----------------
__device__ signed char g_zb[(size_t)B_MAX * C_DIM];   // 16 MB int8
__device__ signed char g_wb[(size_t)K_DIM * C_DIM];   // 2 MB int8
__device__ float g_scores[(size_t)B_MAX * K_DIM];     // 32 MB
__device__ float g_whalf[K_DIM];
__device__ int   g_ind[B_MAX];
__device__ float g_loss;

// refine worklist
#define MAXC 33   // slot 0 = approx best
__device__ int g_nwork;
__device__ int g_work[B_MAX];
__device__ int g_ncand[B_MAX];
__device__ int g_cands[(size_t)B_MAX * MAXC];

__device__ __forceinline__ unsigned pack_s8(float4 v) {
    int a = max(-127, min(127, __float2int_rn(v.x * QSCALE)));
    int b = max(-127, min(127, __float2int_rn(v.y * QSCALE)));
    int c = max(-127, min(127, __float2int_rn(v.z * QSCALE)));
    int d = max(-127, min(127, __float2int_rn(v.w * QSCALE)));
    return (unsigned)(a & 0xff) | ((unsigned)(b & 0xff) << 8)
         | ((unsigned)(c & 0xff) << 16) | ((unsigned)(d & 0xff) << 24);
}

// ---------------- cvt_z: fp32 -> int8 ----------------
__global__ void cvt_z_k(const float* __restrict__ src, signed char* __restrict__ dst, int n16) {
    int i = blockIdx.x * blockDim.x + threadIdx.x;
    int stride = gridDim.x * blockDim.x;
    const float4* s4 = (const float4*)src;
    for (; i < n16; i += stride) {
        uint4 u;
        u.x = pack_s8(s4[i * 4 + 0]);
        u.y = pack_s8(s4[i * 4 + 1]);
        u.z = pack_s8(s4[i * 4 + 2]);
        u.w = pack_s8(s4[i * 4 + 3]);
        ((uint4*)dst)[i] = u;
    }
}

// ---------------- prep_w: fp32->int8 + 0.5*||w||^2 (exact) + zero counters ----------------
__global__ __launch_bounds__(256) void prep_w_k(const float* __restrict__ w,
                                                signed char* __restrict__ wb)
{
    const int k = blockIdx.x;
    const int t = threadIdx.x;
    if (k == 0 && t == 0) { g_loss = 0.0f; g_nwork = 0; }

    const float4* wr = (const float4*)(w + (size_t)k * C_DIM);
    float4 a = wr[t * 2];
    float4 b = wr[t * 2 + 1];

    uint2 u;
    u.x = pack_s8(a);
    u.y = pack_s8(b);
    ((uint2*)(wb + (size_t)k * C_DIM))[t] = u;

    float s = a.x * a.x + a.y * a.y + a.z * a.z + a.w * a.w
            + b.x * b.x + b.y * b.y + b.z * b.z + b.w * b.w;
    __shared__ float red[256];
    red[t] = s;
    __syncthreads();
    for (int o = 128; o > 0; o >>= 1) {
        if (t < o) red[t] += red[t + o];
        __syncthreads();
    }
    if (t == 0) g_whalf[k] = 0.5f * red[0];
}

// ---------------- int8 mma.sync GEMM: scores = (zq . wq^T) / QSCALE^2 ----------------
#define BM 128
#define BN 128
#define BKB 128
#define STAGES 3
#define A_ST (BM * BKB)
#define B_ST (BN * BKB)
#define GSMEM (STAGES * (A_ST + B_ST) + 1024)
#define NITER (C_DIM / BKB)   // 16

#define SWZ128(off) ((off) ^ (((off) >> 3) & 0x70))

__device__ __forceinline__ unsigned smem_u32(const void* p) {
    unsigned a;
    asm("{ .reg .u64 t; cvta.to.shared.u64 t, %1; cvt.u32.u64 %0, t; }" : "=r"(a) : "l"(p));
    return a;
}
__device__ __forceinline__ void cp16(unsigned s, const void* g) {
    asm volatile("cp.async.cg.shared.global [%0], [%1], 16;" :: "r"(s), "l"(g));
}
__device__ __forceinline__ void ldm4(unsigned* d, unsigned addr) {
    asm volatile("ldmatrix.sync.aligned.m8n8.x4.shared.b16 {%0,%1,%2,%3}, [%4];"
                 : "=r"(d[0]), "=r"(d[1]), "=r"(d[2]), "=r"(d[3]) : "r"(addr));
}
__device__ __forceinline__ void mma_s8(int* c, const unsigned* a, unsigned b0, unsigned b1) {
    asm volatile(
        "mma.sync.aligned.m16n8k32.row.col.s32.s8.s8.s32 "
        "{%0,%1,%2,%3}, {%4,%5,%6,%7}, {%8,%9}, {%0,%1,%2,%3};"
        : "+r"(c[0]), "+r"(c[1]), "+r"(c[2]), "+r"(c[3])
        : "r"(a[0]), "r"(a[1]), "r"(a[2]), "r"(a[3]), "r"(b0), "r"(b1));
}

__global__ __launch_bounds__(256, 2) void gemm_k(
    const signed char* __restrict__ zb,
    const signed char* __restrict__ wb,
    float* __restrict__ scores)
{
    extern __shared__ char dsm[];
    unsigned base = (smem_u32(dsm) + 1023u) & ~1023u;
    const unsigned aB = base;
    const unsigned bB = base + STAGES * A_ST;

    const int tid = threadIdx.x;
    const int wid = tid >> 5;
    const int lane = tid & 31;
    const int wm = wid & 3;
    const int wn = wid >> 2;

    const signed char* zrow = zb + (size_t)(blockIdx.x * BM) * C_DIM;
    const signed char* wrow = wb + (size_t)(blockIdx.y * BN) * C_DIM;

    const int lr = tid >> 3;
    const int lc = (tid & 7) * 16;

    int acc[2][8][4];
#pragma unroll
    for (int i = 0; i < 2; i++)
#pragma unroll
        for (int j = 0; j < 8; j++)
#pragma unroll
            for (int q = 0; q < 4; q++) acc[i][j][q] = 0;

#pragma unroll
    for (int s = 0; s < STAGES - 1; s++) {
        int kb = s * BKB;
#pragma unroll
        for (int r = 0; r < 4; r++) {
            int row = r * 32 + lr;
            cp16(aB + s * A_ST + SWZ128((unsigned)(row * BKB + lc)),
                 zrow + (size_t)row * C_DIM + kb + lc);
            cp16(bB + s * B_ST + SWZ128((unsigned)(row * BKB + lc)),
                 wrow + (size_t)row * C_DIM + kb + lc);
        }
        asm volatile("cp.async.commit_group;");
    }

    for (int i = 0; i < NITER; i++) {
        asm volatile("cp.async.wait_group %0;" :: "n"(STAGES - 2));
        __syncthreads();

        if (i + STAGES - 1 < NITER) {
            int s = (i + STAGES - 1) % STAGES;
            int kb = (i + STAGES - 1) * BKB;
#pragma unroll
            for (int r = 0; r < 4; r++) {
                int row = r * 32 + lr;
                cp16(aB + s * A_ST + SWZ128((unsigned)(row * BKB + lc)),
                     zrow + (size_t)row * C_DIM + kb + lc);
                cp16(bB + s * B_ST + SWZ128((unsigned)(row * BKB + lc)),
                     wrow + (size_t)row * C_DIM + kb + lc);
            }
        }
        asm volatile("cp.async.commit_group;");

        const unsigned aS = aB + (i % STAGES) * A_ST;
        const unsigned bS = bB + (i % STAGES) * B_ST;
        const int lrow = lane & 15;
        const int lhalf = (lane >> 4) * 16;

#pragma unroll
        for (int kk = 0; kk < 4; kk++) {
            const int kbyte = kk * 32;
            unsigned af[2][4];
#pragma unroll
            for (int mt = 0; mt < 2; mt++) {
                int row = wm * 32 + mt * 16 + lrow;
                ldm4(af[mt], aS + SWZ128((unsigned)(row * BKB + kbyte + lhalf)));
            }
            unsigned bf[4][4];
#pragma unroll
            for (int nt2 = 0; nt2 < 4; nt2++) {
                int row = wn * 64 + nt2 * 16 + lrow;
                ldm4(bf[nt2], bS + SWZ128((unsigned)(row * BKB + kbyte + lhalf)));
            }
#pragma unroll
            for (int mt = 0; mt < 2; mt++)
#pragma unroll
                for (int nt = 0; nt < 8; nt++) {
                    const unsigned* bv = bf[nt >> 1];
                    unsigned b0 = (nt & 1) ? bv[1] : bv[0];
                    unsigned b1 = (nt & 1) ? bv[3] : bv[2];
                    mma_s8(acc[mt][nt], af[mt], b0, b1);
                }
        }
    }

    const int r0 = blockIdx.x * BM + wm * 32 + (lane >> 2);
    const int c0 = blockIdx.y * BN + wn * 64 + (lane & 3) * 2;
#pragma unroll
    for (int mt = 0; mt < 2; mt++) {
#pragma unroll
        for (int nt = 0; nt < 8; nt++) {
            float* p = scores + (size_t)(r0 + mt * 16) * K_DIM + c0 + nt * 8;
            *(float2*)p = make_float2((float)acc[mt][nt][0] * QINV2,
                                      (float)acc[mt][nt][1] * QINV2);
            *(float2*)(p + 8 * K_DIM) = make_float2((float)acc[mt][nt][2] * QINV2,
                                                    (float)acc[mt][nt][3] * QINV2);
        }
    }
}

// ---------------- scan: approx argmax + candidate collection (low-reg, full occ) ----------------
#define MARGIN 8.0f

__global__ __launch_bounds__(256) void scan_k()
{
    const int b = blockIdx.x;
    const int t = threadIdx.x;
    const int lane = t & 31;
    const int wp = t >> 5;

    __shared__ float s_wv[8];
    __shared__ int   s_wi[8];
    __shared__ float s_best;
    __shared__ int   s_besti;
    __shared__ int   s_cnt;

    float4 sc = ((const float4*)(g_scores + (size_t)b * K_DIM))[t];
    float4 wh = ((const float4*)g_whalf)[t];
    float v[4] = { sc.x - wh.x, sc.y - wh.y, sc.z - wh.z, sc.w - wh.w };

    float bv = v[0];
    int bi = 4 * t;
#pragma unroll
    for (int j = 1; j < 4; j++)
        if (v[j] > bv) { bv = v[j]; bi = 4 * t + j; }

    for (int o = 16; o > 0; o >>= 1) {
        float ov = __shfl_down_sync(0xFFFFFFFFu, bv, o);
        int   oi = __shfl_down_sync(0xFFFFFFFFu, bi, o);
        if (ov > bv || (ov == bv && oi < bi)) { bv = ov; bi = oi; }
    }
    if (lane == 0) { s_wv[wp] = bv; s_wi[wp] = bi; }
    if (t == 0) s_cnt = 0;
    __syncthreads();
    if (t == 0) {
        float gb = s_wv[0]; int gi = s_wi[0];
        for (int i2 = 1; i2 < 8; i2++) {
            float ov = s_wv[i2]; int oi = s_wi[i2];
            if (ov > gb || (ov == gb && oi < gi)) { gb = ov; gi = oi; }
        }
        s_best = gb; s_besti = gi;
        g_cands[(size_t)b * MAXC] = gi;
        g_ind[b] = gi;               // final unless refined
    }
    __syncthreads();
    const float th = s_best - MARGIN;
    const int gbesti = s_besti;

#pragma unroll
    for (int j = 0; j < 4; j++) {
        int k = 4 * t + j;
        if (v[j] >= th && k != gbesti) {
            int p = atomicAdd(&s_cnt, 1);
            if (p < MAXC - 1) g_cands[(size_t)b * MAXC + 1 + p] = k;
        }
    }
    __syncthreads();
    if (t == 0 && s_cnt > 0) {
        int nc = s_cnt < (MAXC - 1) ? s_cnt : (MAXC - 1);
        g_ncand[b] = nc + 1;
        int slot = atomicAdd(&g_nwork, 1);
        g_work[slot] = b;
    }
}

// ---------------- refine: exact fp32 dots for worklist rows ----------------
__global__ __launch_bounds__(128) void refine_k(const float* __restrict__ z,
                                                const float* __restrict__ w)
{
    const int t = threadIdx.x;
    const int lane = t & 31;
    const int wp = t >> 5;

    __shared__ float s_z[C_DIM];
    __shared__ float s_res[MAXC];
    __shared__ int   s_ks[MAXC];

    const int nwork = g_nwork;
    for (int item = blockIdx.x; item < nwork; item += gridDim.x) {
        const int b = g_work[item];
        const int total = g_ncand[b];

        // load z row to smem (8 KB)
        const float4* zr4 = (const float4*)(z + (size_t)b * C_DIM);
#pragma unroll
        for (int d = 0; d < 4; d++)
            ((float4*)s_z)[t + d * 128] = zr4[t + d * 128];
        __syncthreads();

        // one candidate per warp
        for (int ci = wp; ci < total; ci += 4) {
            int k = g_cands[(size_t)b * MAXC + ci];
            const float4* wr4 = (const float4*)(w + (size_t)k * C_DIM);
            float p = 0.0f;
#pragma unroll
            for (int d = 0; d < 16; d++) {
                float4 wv = wr4[lane + d * 32];
                float4 zv = ((const float4*)s_z)[lane + d * 32];
                p += zv.x * wv.x + zv.y * wv.y + zv.z * wv.z + zv.w * wv.w;
            }
            for (int o = 16; o > 0; o >>= 1) p += __shfl_down_sync(0xFFFFFFFFu, p, o);
            if (lane == 0) { s_res[ci] = p - g_whalf[k]; s_ks[ci] = k; }
        }
        __syncthreads();
        if (t == 0) {
            float ebv = -3.4e38f; int ebi = 0;
            for (int ci = 0; ci < total; ci++) {
                float s = s_res[ci]; int k = s_ks[ci];
                if (s > ebv || (s == ebv && k < ebi)) { ebv = s; ebi = k; }
            }
            g_ind[b] = ebi;
        }
        __syncthreads();
    }
}

// ---------------- gather z_q = w[ind], exact sum((w[ind]-z)^2) ----------------
__global__ __launch_bounds__(256) void gather_k(const float* __restrict__ z,
                                                const float* __restrict__ w,
                                                float* __restrict__ out)
{
    int b = blockIdx.x;
    int ind = g_ind[b];
    const float4* wr = (const float4*)(w + (size_t)ind * C_DIM);
    const float4* zr = (const float4*)(z + (size_t)b * C_DIM);
    float4* o4 = (float4*)(out + (size_t)b * C_DIM);

    float s = 0.0f;
#pragma unroll
    for (int c = threadIdx.x; c < C_DIM / 4; c += 256) {
        float4 wv = __ldg(&wr[c]);
        float4 zv;
        asm("ld.global.cs.v4.f32 {%0,%1,%2,%3}, [%4];"
            : "=f"(zv.x), "=f"(zv.y), "=f"(zv.z), "=f"(zv.w) : "l"(zr + c));
        asm volatile("st.global.cs.v4.f32 [%0], {%1,%2,%3,%4};"
            :: "l"(o4 + c), "f"(wv.x), "f"(wv.y), "f"(wv.z), "f"(wv.w));
        float d0 = wv.x - zv.x, d1 = wv.y - zv.y, d2 = wv.z - zv.z, d3 = wv.w - zv.w;
        s += d0 * d0 + d1 * d1 + d2 * d2 + d3 * d3;
    }
    for (int o = 16; o > 0; o >>= 1) s += __shfl_down_sync(0xFFFFFFFFu, s, o);
    __shared__ float red[8];
    if ((threadIdx.x & 31) == 0) red[threadIdx.x >> 5] = s;
    __syncthreads();
    if (threadIdx.x == 0) {
        float tot = 0.0f;
        for (int i = 0; i < 8; i++) tot += red[i];
        atomicAdd(&g_loss, tot);
    }
}

__global__ void fin_k(float* out, int loss_idx, float inv_n) {
    out[loss_idx] = 12.5f * g_loss * inv_n;   // KLD_SCALE*(1+COMMITMENT_COST)*mse
}

extern "C" void kernel_launch(void* const* d_in, const int* in_sizes, int n_in,
                              void* d_out, int out_size)
{
    const float* z = (const float*)d_in[0];
    const float* w = (const float*)d_in[1];
    float* out = (float*)d_out;
    const int B = in_sizes[0] / C_DIM;   // 8192

    void* p_zb; cudaGetSymbolAddress(&p_zb, g_zb);
    void* p_wb; cudaGetSymbolAddress(&p_wb, g_wb);
    void* p_sc; cudaGetSymbolAddress(&p_sc, g_scores);

    cudaFuncSetAttribute(gemm_k, cudaFuncAttributeMaxDynamicSharedMemorySize, GSMEM);

    cvt_z_k<<<2048, 256>>>(z, (signed char*)p_zb, B * C_DIM / 16);
    prep_w_k<<<K_DIM, 256>>>(w, (signed char*)p_wb);

    dim3 ggrid(B / BM, K_DIM / BN);
    gemm_k<<<ggrid, 256, GSMEM>>>((const signed char*)p_zb,
                                  (const signed char*)p_wb,
                                  (float*)p_sc);

    scan_k<<<B, 256>>>();
    refine_k<<<512, 128>>>(z, w);
    gather_k<<<B, 256>>>(z, w, out);
    fin_k<<<1, 1>>>(out, out_size - 1, 1.0f / ((float)B * (float)C_DIM));
}

// round 10
// speedup vs baseline: 1.8390x; 1.1122x over previous
#include <cuda_runtime.h>
#include <cuda_fp16.h>

// Problem: B=8192, C = N*D = 2048, K = 1024
#define C_DIM 2048
#define K_DIM 1024
#define B_MAX 8192

#define QSCALE 23.0f
#define QINV2 (1.0f / (QSCALE * QSCALE))

// ---------------- device scratch ----------------
__device__ signed char g_zb[(size_t)B_MAX * C_DIM];   // 16 MB int8
__device__ signed char g_wb[(size_t)K_DIM * C_DIM];   // 2 MB int8
__device__ __half g_scores[(size_t)B_MAX * K_DIM];    // 16 MB fp16 scores (dot - 0.5||w||^2 ... raw dot)
__device__ float g_whalf[K_DIM];
__device__ float g_znorm[B_MAX];
__device__ int   g_ind[B_MAX];          // approx best (final if not refined)
__device__ float g_bestsc[B_MAX];       // approx best score (for loss dot if not refined)
__device__ unsigned char g_flag[B_MAX]; // 1 if refined
__device__ float g_loss;

// refine pair worklist
#define MAXC 33
__device__ int g_npairs;
__device__ int g_pairs[(size_t)B_MAX * 8];            // (b<<10)|k ; avg ~1 pair/row, 8x headroom
__device__ unsigned long long g_best[B_MAX];          // packed (orderable score, ~k)

__device__ __forceinline__ unsigned pack_s8(float4 v) {
    int a = max(-127, min(127, __float2int_rn(v.x * QSCALE)));
    int b = max(-127, min(127, __float2int_rn(v.y * QSCALE)));
    int c = max(-127, min(127, __float2int_rn(v.z * QSCALE)));
    int d = max(-127, min(127, __float2int_rn(v.w * QSCALE)));
    return (unsigned)(a & 0xff) | ((unsigned)(b & 0xff) << 8)
         | ((unsigned)(c & 0xff) << 16) | ((unsigned)(d & 0xff) << 24);
}

// ---------------- cvt_z: fp32 -> int8, one block per row, + ||z||^2 ----------------
__global__ __launch_bounds__(256) void cvt_z_k(const float* __restrict__ z,
                                               signed char* __restrict__ zb)
{
    const int b = blockIdx.x;
    const int t = threadIdx.x;
    const float4* zr = (const float4*)(z + (size_t)b * C_DIM);
    float4 a = zr[t * 2];
    float4 c = zr[t * 2 + 1];

    uint2 u;
    u.x = pack_s8(a);
    u.y = pack_s8(c);
    ((uint2*)(zb + (size_t)b * C_DIM))[t] = u;

    float s = a.x * a.x + a.y * a.y + a.z * a.z + a.w * a.w
            + c.x * c.x + c.y * c.y + c.z * c.z + c.w * c.w;
    for (int o = 16; o > 0; o >>= 1) s += __shfl_down_sync(0xFFFFFFFFu, s, o);
    __shared__ float red[8];
    if ((t & 31) == 0) red[t >> 5] = s;
    __syncthreads();
    if (t == 0) {
        float tot = 0.0f;
        for (int i = 0; i < 8; i++) tot += red[i];
        g_znorm[b] = tot;
    }
}

// ---------------- prep_w: fp32->int8 + 0.5*||w||^2 + zero counters ----------------
__global__ __launch_bounds__(256) void prep_w_k(const float* __restrict__ w,
                                                signed char* __restrict__ wb)
{
    const int k = blockIdx.x;
    const int t = threadIdx.x;
    if (k == 0 && t == 0) { g_loss = 0.0f; g_npairs = 0; }

    const float4* wr = (const float4*)(w + (size_t)k * C_DIM);
    float4 a = wr[t * 2];
    float4 b = wr[t * 2 + 1];

    uint2 u;
    u.x = pack_s8(a);
    u.y = pack_s8(b);
    ((uint2*)(wb + (size_t)k * C_DIM))[t] = u;

    float s = a.x * a.x + a.y * a.y + a.z * a.z + a.w * a.w
            + b.x * b.x + b.y * b.y + b.z * b.z + b.w * b.w;
    for (int o = 16; o > 0; o >>= 1) s += __shfl_down_sync(0xFFFFFFFFu, s, o);
    __shared__ float red[8];
    if ((t & 31) == 0) red[t >> 5] = s;
    __syncthreads();
    if (t == 0) {
        float tot = 0.0f;
        for (int i = 0; i < 8; i++) tot += red[i];
        g_whalf[k] = 0.5f * tot;
    }
}

// ---------------- int8 mma.sync GEMM: scores(fp16) = (zq . wq^T) / QSCALE^2 ----------------
#define BM 128
#define BN 128
#define BKB 128
#define STAGES 3
#define A_ST (BM * BKB)
#define B_ST (BN * BKB)
#define GSMEM (STAGES * (A_ST + B_ST) + 1024)
#define NITER (C_DIM / BKB)   // 16

#define SWZ128(off) ((off) ^ (((off) >> 3) & 0x70))

__device__ __forceinline__ unsigned smem_u32(const void* p) {
    unsigned a;
    asm("{ .reg .u64 t; cvta.to.shared.u64 t, %1; cvt.u32.u64 %0, t; }" : "=r"(a) : "l"(p));
    return a;
}
__device__ __forceinline__ void cp16(unsigned s, const void* g) {
    asm volatile("cp.async.cg.shared.global [%0], [%1], 16;" :: "r"(s), "l"(g));
}
__device__ __forceinline__ void ldm4(unsigned* d, unsigned addr) {
    asm volatile("ldmatrix.sync.aligned.m8n8.x4.shared.b16 {%0,%1,%2,%3}, [%4];"
                 : "=r"(d[0]), "=r"(d[1]), "=r"(d[2]), "=r"(d[3]) : "r"(addr));
}
__device__ __forceinline__ void mma_s8(int* c, const unsigned* a, unsigned b0, unsigned b1) {
    asm volatile(
        "mma.sync.aligned.m16n8k32.row.col.s32.s8.s8.s32 "
        "{%0,%1,%2,%3}, {%4,%5,%6,%7}, {%8,%9}, {%0,%1,%2,%3};"
        : "+r"(c[0]), "+r"(c[1]), "+r"(c[2]), "+r"(c[3])
        : "r"(a[0]), "r"(a[1]), "r"(a[2]), "r"(a[3]), "r"(b0), "r"(b1));
}

__global__ __launch_bounds__(256, 2) void gemm_k(
    const signed char* __restrict__ zb,
    const signed char* __restrict__ wb,
    __half* __restrict__ scores)
{
    extern __shared__ char dsm[];
    unsigned base = (smem_u32(dsm) + 1023u) & ~1023u;
    const unsigned aB = base;
    const unsigned bB = base + STAGES * A_ST;

    const int tid = threadIdx.x;
    const int wid = tid >> 5;
    const int lane = tid & 31;
    const int wm = wid & 3;
    const int wn = wid >> 2;

    const signed char* zrow = zb + (size_t)(blockIdx.x * BM) * C_DIM;
    const signed char* wrow = wb + (size_t)(blockIdx.y * BN) * C_DIM;

    const int lr = tid >> 3;
    const int lc = (tid & 7) * 16;

    int acc[2][8][4];
#pragma unroll
    for (int i = 0; i < 2; i++)
#pragma unroll
        for (int j = 0; j < 8; j++)
#pragma unroll
            for (int q = 0; q < 4; q++) acc[i][j][q] = 0;

#pragma unroll
    for (int s = 0; s < STAGES - 1; s++) {
        int kb = s * BKB;
#pragma unroll
        for (int r = 0; r < 4; r++) {
            int row = r * 32 + lr;
            cp16(aB + s * A_ST + SWZ128((unsigned)(row * BKB + lc)),
                 zrow + (size_t)row * C_DIM + kb + lc);
            cp16(bB + s * B_ST + SWZ128((unsigned)(row * BKB + lc)),
                 wrow + (size_t)row * C_DIM + kb + lc);
        }
        asm volatile("cp.async.commit_group;");
    }

    for (int i = 0; i < NITER; i++) {
        asm volatile("cp.async.wait_group %0;" :: "n"(STAGES - 2));
        __syncthreads();

        if (i + STAGES - 1 < NITER) {
            int s = (i + STAGES - 1) % STAGES;
            int kb = (i + STAGES - 1) * BKB;
#pragma unroll
            for (int r = 0; r < 4; r++) {
                int row = r * 32 + lr;
                cp16(aB + s * A_ST + SWZ128((unsigned)(row * BKB + lc)),
                     zrow + (size_t)row * C_DIM + kb + lc);
                cp16(bB + s * B_ST + SWZ128((unsigned)(row * BKB + lc)),
                     wrow + (size_t)row * C_DIM + kb + lc);
            }
        }
        asm volatile("cp.async.commit_group;");

        const unsigned aS = aB + (i % STAGES) * A_ST;
        const unsigned bS = bB + (i % STAGES) * B_ST;
        const int lrow = lane & 15;
        const int lhalf = (lane >> 4) * 16;

#pragma unroll
        for (int kk = 0; kk < 4; kk++) {
            const int kbyte = kk * 32;
            unsigned af[2][4];
#pragma unroll
            for (int mt = 0; mt < 2; mt++) {
                int row = wm * 32 + mt * 16 + lrow;
                ldm4(af[mt], aS + SWZ128((unsigned)(row * BKB + kbyte + lhalf)));
            }
            unsigned bf[4][4];
#pragma unroll
            for (int nt2 = 0; nt2 < 4; nt2++) {
                int row = wn * 64 + nt2 * 16 + lrow;
                ldm4(bf[nt2], bS + SWZ128((unsigned)(row * BKB + kbyte + lhalf)));
            }
#pragma unroll
            for (int mt = 0; mt < 2; mt++)
#pragma unroll
                for (int nt = 0; nt < 8; nt++) {
                    const unsigned* bv = bf[nt >> 1];
                    unsigned b0 = (nt & 1) ? bv[1] : bv[0];
                    unsigned b1 = (nt & 1) ? bv[3] : bv[2];
                    mma_s8(acc[mt][nt], af[mt], b0, b1);
                }
        }
    }

    const int r0 = blockIdx.x * BM + wm * 32 + (lane >> 2);
    const int c0 = blockIdx.y * BN + wn * 64 + (lane & 3) * 2;
#pragma unroll
    for (int mt = 0; mt < 2; mt++) {
#pragma unroll
        for (int nt = 0; nt < 8; nt++) {
            __half* p = scores + (size_t)(r0 + mt * 16) * K_DIM + c0 + nt * 8;
            *(__half2*)p = __floats2half2_rn((float)acc[mt][nt][0] * QINV2,
                                             (float)acc[mt][nt][1] * QINV2);
            *(__half2*)(p + 8 * K_DIM) = __floats2half2_rn((float)acc[mt][nt][2] * QINV2,
                                                           (float)acc[mt][nt][3] * QINV2);
        }
    }
}

// ---------------- scan: approx argmax + pair collection ----------------
#define MARGIN 8.5f

__global__ __launch_bounds__(256) void scan_k()
{
    const int b = blockIdx.x;
    const int t = threadIdx.x;
    const int lane = t & 31;
    const int wp = t >> 5;

    __shared__ float s_wv[8];
    __shared__ int   s_wi[8];
    __shared__ float s_best;
    __shared__ int   s_besti;
    __shared__ int   s_cnt;
    __shared__ int   s_base;
    __shared__ int   s_cand[MAXC];

    const __half2* srow = (const __half2*)(g_scores + (size_t)b * K_DIM);
    float2 h0 = __half22float2(srow[2 * t]);
    float2 h1 = __half22float2(srow[2 * t + 1]);
    float4 wh = ((const float4*)g_whalf)[t];
    float v[4] = { h0.x - wh.x, h0.y - wh.y, h1.x - wh.z, h1.y - wh.w };

    float bv = v[0];
    int bi = 4 * t;
#pragma unroll
    for (int j = 1; j < 4; j++)
        if (v[j] > bv) { bv = v[j]; bi = 4 * t + j; }

    for (int o = 16; o > 0; o >>= 1) {
        float ov = __shfl_down_sync(0xFFFFFFFFu, bv, o);
        int   oi = __shfl_down_sync(0xFFFFFFFFu, bi, o);
        if (ov > bv || (ov == bv && oi < bi)) { bv = ov; bi = oi; }
    }
    if (lane == 0) { s_wv[wp] = bv; s_wi[wp] = bi; }
    if (t == 0) s_cnt = 0;
    __syncthreads();
    if (t == 0) {
        float gb = s_wv[0]; int gi = s_wi[0];
        for (int i2 = 1; i2 < 8; i2++) {
            float ov = s_wv[i2]; int oi = s_wi[i2];
            if (ov > gb || (ov == gb && oi < gi)) { gb = ov; gi = oi; }
        }
        s_best = gb; s_besti = gi;
        s_cand[0] = gi;
        g_ind[b] = gi;
        g_bestsc[b] = gb;
    }
    __syncthreads();
    const float th = s_best - MARGIN;
    const int gbesti = s_besti;

#pragma unroll
    for (int j = 0; j < 4; j++) {
        int k = 4 * t + j;
        if (v[j] >= th && k != gbesti) {
            int p = atomicAdd(&s_cnt, 1);
            if (p < MAXC - 1) s_cand[p + 1] = k;
        }
    }
    __syncthreads();
    int nc = s_cnt < (MAXC - 1) ? s_cnt : (MAXC - 1);
    if (t == 0) {
        if (nc > 0) {
            g_flag[b] = 1;
            g_best[b] = 0ULL;
            s_base = atomicAdd(&g_npairs, nc + 1);
        } else {
            g_flag[b] = 0;
        }
    }
    __syncthreads();
    if (nc > 0 && t <= nc) {
        g_pairs[s_base + t] = (b << 10) | s_cand[t];
    }
}

// ---------------- refine: one warp per (row, candidate) pair, exact fp32 dot ----------------
__global__ __launch_bounds__(128) void refine_k(const float* __restrict__ z,
                                                const float* __restrict__ w)
{
    const int lane = threadIdx.x & 31;
    const int wp = threadIdx.x >> 5;
    const int npairs = g_npairs;

    for (int pi = blockIdx.x * 4 + wp; pi < npairs; pi += gridDim.x * 4) {
        const int pk = g_pairs[pi];
        const int b = pk >> 10;
        const int k = pk & 1023;

        const float4* zr4 = (const float4*)(z + (size_t)b * C_DIM);
        const float4* wr4 = (const float4*)(w + (size_t)k * C_DIM);
        float p = 0.0f;
#pragma unroll
        for (int d = 0; d < 16; d++) {
            float4 zv = zr4[lane + d * 32];
            float4 wv = wr4[lane + d * 32];
            p += zv.x * wv.x + zv.y * wv.y + zv.z * wv.z + zv.w * wv.w;
        }
        for (int o = 16; o > 0; o >>= 1) p += __shfl_down_sync(0xFFFFFFFFu, p, o);
        if (lane == 0) {
            float score = p - g_whalf[k];
            unsigned ub = __float_as_uint(score);
            ub = (ub & 0x80000000u) ? ~ub : (ub | 0x80000000u);
            unsigned long long packed = ((unsigned long long)ub << 32) | (unsigned)(~(unsigned)k);
            atomicMax(&g_best[b], packed);
        }
    }
}

// ---------------- gather: out = w[ind]; loss via norm identity ----------------
__global__ __launch_bounds__(256) void gather_k(const float* __restrict__ w,
                                                float* __restrict__ out)
{
    const int b = blockIdx.x;
    const int t = threadIdx.x;

    __shared__ int s_ind;
    if (t == 0) {
        int ind;
        float score;
        if (g_flag[b]) {
            unsigned long long pb = g_best[b];
            ind = (int)(~(unsigned)(pb & 0xFFFFFFFFu));
            unsigned ub = (unsigned)(pb >> 32);
            score = (ub & 0x80000000u) ? __uint_as_float(ub ^ 0x80000000u)
                                       : __uint_as_float(~ub);
        } else {
            ind = g_ind[b];
            score = g_bestsc[b];
        }
        s_ind = ind;
        // dot = score + whalf; loss_row = ||z||^2 - 2*dot + 2*whalf
        float wh = g_whalf[ind];
        float dot = score + wh;
        float rl = g_znorm[b] - 2.0f * dot + 2.0f * wh;
        atomicAdd(&g_loss, rl);
    }
    __syncthreads();
    const int ind = s_ind;

    const float4* wr = (const float4*)(w + (size_t)ind * C_DIM);
    float4* o4 = (float4*)(out + (size_t)b * C_DIM);
#pragma unroll
    for (int c = t; c < C_DIM / 4; c += 256) {
        float4 wv = __ldg(&wr[c]);
        asm volatile("st.global.cs.v4.f32 [%0], {%1,%2,%3,%4};"
            :: "l"(o4 + c), "f"(wv.x), "f"(wv.y), "f"(wv.z), "f"(wv.w));
    }
}

__global__ void fin_k(float* out, int loss_idx, float inv_n) {
    out[loss_idx] = 12.5f * g_loss * inv_n;   // KLD_SCALE*(1+COMMITMENT_COST)*mse
}

extern "C" void kernel_launch(void* const* d_in, const int* in_sizes, int n_in,
                              void* d_out, int out_size)
{
    const float* z = (const float*)d_in[0];
    const float* w = (const float*)d_in[1];
    float* out = (float*)d_out;
    const int B = in_sizes[0] / C_DIM;   // 8192

    void* p_zb; cudaGetSymbolAddress(&p_zb, g_zb);
    void* p_wb; cudaGetSymbolAddress(&p_wb, g_wb);
    void* p_sc; cudaGetSymbolAddress(&p_sc, g_scores);

    cudaFuncSetAttribute(gemm_k, cudaFuncAttributeMaxDynamicSharedMemorySize, GSMEM);

    cvt_z_k<<<B, 256>>>(z, (signed char*)p_zb);
    prep_w_k<<<K_DIM, 256>>>(w, (signed char*)p_wb);

    dim3 ggrid(B / BM, K_DIM / BN);
    gemm_k<<<ggrid, 256, GSMEM>>>((const signed char*)p_zb,
                                  (const signed char*)p_wb,
                                  (__half*)p_sc);

    scan_k<<<B, 256>>>();
    refine_k<<<592, 128>>>(z, w);
    gather_k<<<B, 256>>>(w, out);
    fin_k<<<1, 1>>>(out, out_size - 1, 1.0f / ((float)B * (float)C_DIM));
}

// round 11
// speedup vs baseline: 1.8960x; 1.0310x over previous
#include <cuda_runtime.h>
#include <cuda_fp16.h>

// Problem: B=8192, C = N*D = 2048, K = 1024
#define C_DIM 2048
#define K_DIM 1024
#define B_MAX 8192

#define QSCALE 23.0f
#define QINV2 (1.0f / (QSCALE * QSCALE))
#define SHIFT 1024.0f

// ---------------- device scratch ----------------
__device__ signed char g_zb[(size_t)B_MAX * C_DIM];   // 16 MB int8
__device__ signed char g_wb[(size_t)K_DIM * C_DIM];   // 2 MB int8
__device__ __half g_scores[(size_t)B_MAX * K_DIM];    // 16 MB: dot - whalf + SHIFT
__device__ float g_whalf[K_DIM];
__device__ float g_znorm[B_MAX];
__device__ int   g_ind[B_MAX];
__device__ float g_bestsc[B_MAX];       // stored-form best score (unrefined rows)
__device__ unsigned char g_flag[B_MAX];
__device__ float g_loss;

#define MAXC 33
__device__ int g_npairs;
__device__ int g_pairs[(size_t)B_MAX * 8];
__device__ unsigned long long g_best[B_MAX];   // packed (orderable true score, ~k)

__device__ __forceinline__ unsigned pack_s8(float4 v) {
    int a = max(-127, min(127, __float2int_rn(v.x * QSCALE)));
    int b = max(-127, min(127, __float2int_rn(v.y * QSCALE)));
    int c = max(-127, min(127, __float2int_rn(v.z * QSCALE)));
    int d = max(-127, min(127, __float2int_rn(v.w * QSCALE)));
    return (unsigned)(a & 0xff) | ((unsigned)(b & 0xff) << 8)
         | ((unsigned)(c & 0xff) << 16) | ((unsigned)(d & 0xff) << 24);
}

// ---------------- fused prep: blocks [0,K) -> w rows; [K, K+B) -> z rows ----------------
__global__ __launch_bounds__(256) void prep_k(const float* __restrict__ z,
                                              const float* __restrict__ w,
                                              signed char* __restrict__ zb,
                                              signed char* __restrict__ wb)
{
    const int blk = blockIdx.x;
    const int t = threadIdx.x;
    const bool is_w = blk < K_DIM;
    const int row = is_w ? blk : blk - K_DIM;
    if (blk == 0 && t == 0) { g_loss = 0.0f; g_npairs = 0; }

    const float* src = is_w ? (w + (size_t)row * C_DIM) : (z + (size_t)row * C_DIM);
    signed char* dst = is_w ? (wb + (size_t)row * C_DIM) : (zb + (size_t)row * C_DIM);

    const float4* s4 = (const float4*)src;
    float4 a = s4[t * 2];
    float4 b = s4[t * 2 + 1];

    uint2 u;
    u.x = pack_s8(a);
    u.y = pack_s8(b);
    ((uint2*)dst)[t] = u;

    float s = a.x * a.x + a.y * a.y + a.z * a.z + a.w * a.w
            + b.x * b.x + b.y * b.y + b.z * b.z + b.w * b.w;
    for (int o = 16; o > 0; o >>= 1) s += __shfl_down_sync(0xFFFFFFFFu, s, o);
    __shared__ float red[8];
    if ((t & 31) == 0) red[t >> 5] = s;
    __syncthreads();
    if (t == 0) {
        float tot = 0.0f;
        for (int i = 0; i < 8; i++) tot += red[i];
        if (is_w) g_whalf[row] = 0.5f * tot;
        else      g_znorm[row] = tot;
    }
}

// ---------------- int8 mma.sync GEMM; epilogue stores fp16 (dot - whalf + SHIFT) ----------------
#define BM 128
#define BN 128
#define BKB 128
#define STAGES 3
#define A_ST (BM * BKB)
#define B_ST (BN * BKB)
#define GSMEM (STAGES * (A_ST + B_ST) + 1024)
#define NITER (C_DIM / BKB)   // 16

#define SWZ128(off) ((off) ^ (((off) >> 3) & 0x70))

__device__ __forceinline__ unsigned smem_u32(const void* p) {
    unsigned a;
    asm("{ .reg .u64 t; cvta.to.shared.u64 t, %1; cvt.u32.u64 %0, t; }" : "=r"(a) : "l"(p));
    return a;
}
__device__ __forceinline__ void cp16(unsigned s, const void* g) {
    asm volatile("cp.async.cg.shared.global [%0], [%1], 16;" :: "r"(s), "l"(g));
}
__device__ __forceinline__ void ldm4(unsigned* d, unsigned addr) {
    asm volatile("ldmatrix.sync.aligned.m8n8.x4.shared.b16 {%0,%1,%2,%3}, [%4];"
                 : "=r"(d[0]), "=r"(d[1]), "=r"(d[2]), "=r"(d[3]) : "r"(addr));
}
__device__ __forceinline__ void mma_s8(int* c, const unsigned* a, unsigned b0, unsigned b1) {
    asm volatile(
        "mma.sync.aligned.m16n8k32.row.col.s32.s8.s8.s32 "
        "{%0,%1,%2,%3}, {%4,%5,%6,%7}, {%8,%9}, {%0,%1,%2,%3};"
        : "+r"(c[0]), "+r"(c[1]), "+r"(c[2]), "+r"(c[3])
        : "r"(a[0]), "r"(a[1]), "r"(a[2]), "r"(a[3]), "r"(b0), "r"(b1));
}

__global__ __launch_bounds__(256, 2) void gemm_k(
    const signed char* __restrict__ zb,
    const signed char* __restrict__ wb,
    __half* __restrict__ scores)
{
    extern __shared__ char dsm[];
    unsigned base = (smem_u32(dsm) + 1023u) & ~1023u;
    const unsigned aB = base;
    const unsigned bB = base + STAGES * A_ST;

    const int tid = threadIdx.x;
    const int wid = tid >> 5;
    const int lane = tid & 31;
    const int wm = wid & 3;
    const int wn = wid >> 2;

    const signed char* zrow = zb + (size_t)(blockIdx.x * BM) * C_DIM;
    const signed char* wrow = wb + (size_t)(blockIdx.y * BN) * C_DIM;

    const int lr = tid >> 3;
    const int lc = (tid & 7) * 16;

    int acc[2][8][4];
#pragma unroll
    for (int i = 0; i < 2; i++)
#pragma unroll
        for (int j = 0; j < 8; j++)
#pragma unroll
            for (int q = 0; q < 4; q++) acc[i][j][q] = 0;

#pragma unroll
    for (int s = 0; s < STAGES - 1; s++) {
        int kb = s * BKB;
#pragma unroll
        for (int r = 0; r < 4; r++) {
            int row = r * 32 + lr;
            cp16(aB + s * A_ST + SWZ128((unsigned)(row * BKB + lc)),
                 zrow + (size_t)row * C_DIM + kb + lc);
            cp16(bB + s * B_ST + SWZ128((unsigned)(row * BKB + lc)),
                 wrow + (size_t)row * C_DIM + kb + lc);
        }
        asm volatile("cp.async.commit_group;");
    }

    for (int i = 0; i < NITER; i++) {
        asm volatile("cp.async.wait_group %0;" :: "n"(STAGES - 2));
        __syncthreads();

        if (i + STAGES - 1 < NITER) {
            int s = (i + STAGES - 1) % STAGES;
            int kb = (i + STAGES - 1) * BKB;
#pragma unroll
            for (int r = 0; r < 4; r++) {
                int row = r * 32 + lr;
                cp16(aB + s * A_ST + SWZ128((unsigned)(row * BKB + lc)),
                     zrow + (size_t)row * C_DIM + kb + lc);
                cp16(bB + s * B_ST + SWZ128((unsigned)(row * BKB + lc)),
                     wrow + (size_t)row * C_DIM + kb + lc);
            }
        }
        asm volatile("cp.async.commit_group;");

        const unsigned aS = aB + (i % STAGES) * A_ST;
        const unsigned bS = bB + (i % STAGES) * B_ST;
        const int lrow = lane & 15;
        const int lhalf = (lane >> 4) * 16;

#pragma unroll
        for (int kk = 0; kk < 4; kk++) {
            const int kbyte = kk * 32;
            unsigned af[2][4];
#pragma unroll
            for (int mt = 0; mt < 2; mt++) {
                int row = wm * 32 + mt * 16 + lrow;
                ldm4(af[mt], aS + SWZ128((unsigned)(row * BKB + kbyte + lhalf)));
            }
            unsigned bf[4][4];
#pragma unroll
            for (int nt2 = 0; nt2 < 4; nt2++) {
                int row = wn * 64 + nt2 * 16 + lrow;
                ldm4(bf[nt2], bS + SWZ128((unsigned)(row * BKB + kbyte + lhalf)));
            }
#pragma unroll
            for (int mt = 0; mt < 2; mt++)
#pragma unroll
                for (int nt = 0; nt < 8; nt++) {
                    const unsigned* bv = bf[nt >> 1];
                    unsigned b0 = (nt & 1) ? bv[1] : bv[0];
                    unsigned b1 = (nt & 1) ? bv[3] : bv[2];
                    mma_s8(acc[mt][nt], af[mt], b0, b1);
                }
        }
    }

    const int r0 = blockIdx.x * BM + wm * 32 + (lane >> 2);
    const int c0 = blockIdx.y * BN + wn * 64 + (lane & 3) * 2;
#pragma unroll
    for (int mt = 0; mt < 2; mt++) {
#pragma unroll
        for (int nt = 0; nt < 8; nt++) {
            const int c = c0 + nt * 8;
            float wh0 = g_whalf[c];
            float wh1 = g_whalf[c + 1];
            __half* p = scores + (size_t)(r0 + mt * 16) * K_DIM + c;
            *(__half2*)p = __floats2half2_rn(
                (float)acc[mt][nt][0] * QINV2 - wh0 + SHIFT,
                (float)acc[mt][nt][1] * QINV2 - wh1 + SHIFT);
            *(__half2*)(p + 8 * K_DIM) = __floats2half2_rn(
                (float)acc[mt][nt][2] * QINV2 - wh0 + SHIFT,
                (float)acc[mt][nt][3] * QINV2 - wh1 + SHIFT);
        }
    }
}

// ---------------- scan: index-free max + candidate collection ----------------
#define MARGIN 8.5f

__global__ __launch_bounds__(256) void scan_k()
{
    const int b = blockIdx.x;
    const int t = threadIdx.x;
    const int lane = t & 31;
    const int wp = t >> 5;

    __shared__ float s_wv[8];
    __shared__ float s_best;
    __shared__ int   s_besti;
    __shared__ int   s_cnt;
    __shared__ int   s_base;
    __shared__ int   s_cand[MAXC];

    // 4 scores per thread: k = 4t..4t+3
    uint2 raw = ((const uint2*)(g_scores + (size_t)b * K_DIM))[t];
    __half2 p0 = *(__half2*)&raw.x;
    __half2 p1 = *(__half2*)&raw.y;

    // index-free max
    __half2 m2 = __hmax2(p0, p1);
    float2 mf = __half22float2(m2);
    float mv = fmaxf(mf.x, mf.y);
    for (int o = 16; o > 0; o >>= 1)
        mv = fmaxf(mv, __shfl_down_sync(0xFFFFFFFFu, mv, o));
    if (lane == 0) s_wv[wp] = mv;
    if (t == 0) { s_cnt = 0; s_besti = K_DIM; }
    __syncthreads();
    if (t == 0) {
        float gb = s_wv[0];
        for (int i2 = 1; i2 < 8; i2++) gb = fmaxf(gb, s_wv[i2]);
        s_best = gb;
    }
    __syncthreads();
    const float best = s_best;
    const float th = best - MARGIN;

    float2 a = __half22float2(p0);
    float2 c = __half22float2(p1);
    float v[4] = { a.x, a.y, c.x, c.y };
#pragma unroll
    for (int j = 0; j < 4; j++) {
        if (v[j] >= th) {
            int p = atomicAdd(&s_cnt, 1);
            if (p < MAXC) s_cand[p] = 4 * t + j;
            if (v[j] == best) atomicMin(&s_besti, 4 * t + j);
        }
    }
    __syncthreads();
    int cnt = s_cnt < MAXC ? s_cnt : MAXC;
    if (t == 0) {
        g_ind[b] = s_besti;
        g_bestsc[b] = best;
        if (cnt > 1) {
            g_flag[b] = 1;
            g_best[b] = 0ULL;
            s_base = atomicAdd(&g_npairs, cnt);
        } else {
            g_flag[b] = 0;
        }
    }
    __syncthreads();
    if (cnt > 1 && t < cnt)
        g_pairs[s_base + t] = (b << 10) | s_cand[t];
}

// ---------------- refine: one warp per pair, exact fp32 dot ----------------
__global__ __launch_bounds__(128) void refine_k(const float* __restrict__ z,
                                                const float* __restrict__ w)
{
    const int lane = threadIdx.x & 31;
    const int wp = threadIdx.x >> 5;
    const int npairs = g_npairs;

    for (int pi = blockIdx.x * 4 + wp; pi < npairs; pi += gridDim.x * 4) {
        const int pk = g_pairs[pi];
        const int b = pk >> 10;
        const int k = pk & 1023;

        const float4* zr4 = (const float4*)(z + (size_t)b * C_DIM);
        const float4* wr4 = (const float4*)(w + (size_t)k * C_DIM);
        float p = 0.0f;
#pragma unroll
        for (int d = 0; d < 16; d++) {
            float4 zv = zr4[lane + d * 32];
            float4 wv = wr4[lane + d * 32];
            p += zv.x * wv.x + zv.y * wv.y + zv.z * wv.z + zv.w * wv.w;
        }
        for (int o = 16; o > 0; o >>= 1) p += __shfl_down_sync(0xFFFFFFFFu, p, o);
        if (lane == 0) {
            float score = p - g_whalf[k];          // true adjusted score
            unsigned ub = __float_as_uint(score);
            ub = (ub & 0x80000000u) ? ~ub : (ub | 0x80000000u);
            unsigned long long packed = ((unsigned long long)ub << 32) | (unsigned)(~(unsigned)k);
            atomicMax(&g_best[b], packed);
        }
    }
}

// ---------------- gather: out = w[ind]; loss rl = znorm - 2*score_true ----------------
__global__ __launch_bounds__(256) void gather_k(const float* __restrict__ w,
                                                float* __restrict__ out)
{
    const int b = blockIdx.x;
    const int t = threadIdx.x;

    __shared__ int s_ind;
    if (t == 0) {
        int ind;
        float score_true;
        if (g_flag[b]) {
            unsigned long long pb = g_best[b];
            ind = (int)(~(unsigned)(pb & 0xFFFFFFFFu));
            unsigned ub = (unsigned)(pb >> 32);
            score_true = (ub & 0x80000000u) ? __uint_as_float(ub ^ 0x80000000u)
                                            : __uint_as_float(~ub);
        } else {
            ind = g_ind[b];
            score_true = g_bestsc[b] - SHIFT;
        }
        s_ind = ind;
        atomicAdd(&g_loss, g_znorm[b] - 2.0f * score_true);
    }
    __syncthreads();
    const int ind = s_ind;

    const float4* wr = (const float4*)(w + (size_t)ind * C_DIM);
    float4* o4 = (float4*)(out + (size_t)b * C_DIM);
#pragma unroll
    for (int c = t; c < C_DIM / 4; c += 256) {
        float4 wv = __ldg(&wr[c]);
        asm volatile("st.global.cs.v4.f32 [%0], {%1,%2,%3,%4};"
            :: "l"(o4 + c), "f"(wv.x), "f"(wv.y), "f"(wv.z), "f"(wv.w));
    }
}

__global__ void fin_k(float* out, int loss_idx, float inv_n) {
    out[loss_idx] = 12.5f * g_loss * inv_n;   // KLD_SCALE*(1+COMMITMENT_COST)*mse
}

extern "C" void kernel_launch(void* const* d_in, const int* in_sizes, int n_in,
                              void* d_out, int out_size)
{
    const float* z = (const float*)d_in[0];
    const float* w = (const float*)d_in[1];
    float* out = (float*)d_out;
    const int B = in_sizes[0] / C_DIM;   // 8192

    void* p_zb; cudaGetSymbolAddress(&p_zb, g_zb);
    void* p_wb; cudaGetSymbolAddress(&p_wb, g_wb);
    void* p_sc; cudaGetSymbolAddress(&p_sc, g_scores);

    cudaFuncSetAttribute(gemm_k, cudaFuncAttributeMaxDynamicSharedMemorySize, GSMEM);

    prep_k<<<K_DIM + B, 256>>>(z, w, (signed char*)p_zb, (signed char*)p_wb);

    dim3 ggrid(B / BM, K_DIM / BN);
    gemm_k<<<ggrid, 256, GSMEM>>>((const signed char*)p_zb,
                                  (const signed char*)p_wb,
                                  (__half*)p_sc);

    scan_k<<<B, 256>>>();
    refine_k<<<592, 128>>>(z, w);
    gather_k<<<B, 256>>>(w, out);
    fin_k<<<1, 1>>>(out, out_size - 1, 1.0f / ((float)B * (float)C_DIM));
}

// round 12
// speedup vs baseline: 2.0447x; 1.0784x over previous
#include <cuda_runtime.h>
#include <cuda_fp16.h>

// Problem: B=8192, C = N*D = 2048, K = 1024
#define C_DIM 2048
#define K_DIM 1024
#define B_MAX 8192

#define QSCALE 23.0f
#define QINV2 (1.0f / (QSCALE * QSCALE))
#define SHIFT 1024.0f

// ---------------- device scratch ----------------
__device__ signed char g_zb[(size_t)B_MAX * C_DIM];   // 16 MB int8
__device__ signed char g_wb[(size_t)K_DIM * C_DIM];   // 2 MB int8
__device__ __half g_scores[(size_t)B_MAX * K_DIM];    // 16 MB: dot - whalf + SHIFT
__device__ float g_whalf[K_DIM];
__device__ float g_znorm[B_MAX];
__device__ int   g_ind[B_MAX];
__device__ float g_bestsc[B_MAX];
__device__ unsigned char g_flag[B_MAX];
__device__ float g_loss;

#define MAXC 33
__device__ int g_npairs;
__device__ int g_pairs[(size_t)B_MAX * 8];
__device__ unsigned long long g_best[B_MAX];

__device__ __forceinline__ unsigned pack_s8(float4 v) {
    int a = max(-127, min(127, __float2int_rn(v.x * QSCALE)));
    int b = max(-127, min(127, __float2int_rn(v.y * QSCALE)));
    int c = max(-127, min(127, __float2int_rn(v.z * QSCALE)));
    int d = max(-127, min(127, __float2int_rn(v.w * QSCALE)));
    return (unsigned)(a & 0xff) | ((unsigned)(b & 0xff) << 8)
         | ((unsigned)(c & 0xff) << 16) | ((unsigned)(d & 0xff) << 24);
}

// ---------------- fused prep: blocks [0,K) -> w rows; [K, K+B) -> z rows ----------------
__global__ __launch_bounds__(256) void prep_k(const float* __restrict__ z,
                                              const float* __restrict__ w,
                                              signed char* __restrict__ zb,
                                              signed char* __restrict__ wb)
{
    const int blk = blockIdx.x;
    const int t = threadIdx.x;
    const bool is_w = blk < K_DIM;
    const int row = is_w ? blk : blk - K_DIM;
    if (blk == 0 && t == 0) { g_loss = 0.0f; g_npairs = 0; }

    const float* src = is_w ? (w + (size_t)row * C_DIM) : (z + (size_t)row * C_DIM);
    signed char* dst = is_w ? (wb + (size_t)row * C_DIM) : (zb + (size_t)row * C_DIM);

    const float4* s4 = (const float4*)src;
    float4 a = s4[t * 2];
    float4 b = s4[t * 2 + 1];

    uint2 u;
    u.x = pack_s8(a);
    u.y = pack_s8(b);
    ((uint2*)dst)[t] = u;

    float s = a.x * a.x + a.y * a.y + a.z * a.z + a.w * a.w
            + b.x * b.x + b.y * b.y + b.z * b.z + b.w * b.w;
    for (int o = 16; o > 0; o >>= 1) s += __shfl_down_sync(0xFFFFFFFFu, s, o);
    __shared__ float red[8];
    if ((t & 31) == 0) red[t >> 5] = s;
    __syncthreads();
    if (t == 0) {
        float tot = 0.0f;
        for (int i = 0; i < 8; i++) tot += red[i];
        if (is_w) g_whalf[row] = 0.5f * tot;
        else      g_znorm[row] = tot;
    }
}

// ---------------- int8 mma.sync GEMM; epilogue stores fp16 (dot - whalf + SHIFT) ----------------
#define BM 128
#define BN 128
#define BKB 128
#define STAGES 3
#define A_ST (BM * BKB)
#define B_ST (BN * BKB)
#define GSMEM (STAGES * (A_ST + B_ST) + 1024)
#define NITER (C_DIM / BKB)   // 16

#define SWZ128(off) ((off) ^ (((off) >> 3) & 0x70))

__device__ __forceinline__ unsigned smem_u32(const void* p) {
    unsigned a;
    asm("{ .reg .u64 t; cvta.to.shared.u64 t, %1; cvt.u32.u64 %0, t; }" : "=r"(a) : "l"(p));
    return a;
}
__device__ __forceinline__ void cp16(unsigned s, const void* g) {
    asm volatile("cp.async.cg.shared.global [%0], [%1], 16;" :: "r"(s), "l"(g));
}
__device__ __forceinline__ void ldm4(unsigned* d, unsigned addr) {
    asm volatile("ldmatrix.sync.aligned.m8n8.x4.shared.b16 {%0,%1,%2,%3}, [%4];"
                 : "=r"(d[0]), "=r"(d[1]), "=r"(d[2]), "=r"(d[3]) : "r"(addr));
}
__device__ __forceinline__ void mma_s8(int* c, const unsigned* a, unsigned b0, unsigned b1) {
    asm volatile(
        "mma.sync.aligned.m16n8k32.row.col.s32.s8.s8.s32 "
        "{%0,%1,%2,%3}, {%4,%5,%6,%7}, {%8,%9}, {%0,%1,%2,%3};"
        : "+r"(c[0]), "+r"(c[1]), "+r"(c[2]), "+r"(c[3])
        : "r"(a[0]), "r"(a[1]), "r"(a[2]), "r"(a[3]), "r"(b0), "r"(b1));
}

__global__ __launch_bounds__(256, 2) void gemm_k(
    const signed char* __restrict__ zb,
    const signed char* __restrict__ wb,
    __half* __restrict__ scores)
{
    extern __shared__ char dsm[];
    unsigned base = (smem_u32(dsm) + 1023u) & ~1023u;
    const unsigned aB = base;
    const unsigned bB = base + STAGES * A_ST;

    const int tid = threadIdx.x;
    const int wid = tid >> 5;
    const int lane = tid & 31;
    const int wm = wid & 3;
    const int wn = wid >> 2;

    const signed char* zrow = zb + (size_t)(blockIdx.x * BM) * C_DIM;
    const signed char* wrow = wb + (size_t)(blockIdx.y * BN) * C_DIM;

    const int lr = tid >> 3;
    const int lc = (tid & 7) * 16;

    int acc[2][8][4];
#pragma unroll
    for (int i = 0; i < 2; i++)
#pragma unroll
        for (int j = 0; j < 8; j++)
#pragma unroll
            for (int q = 0; q < 4; q++) acc[i][j][q] = 0;

#pragma unroll
    for (int s = 0; s < STAGES - 1; s++) {
        int kb = s * BKB;
#pragma unroll
        for (int r = 0; r < 4; r++) {
            int row = r * 32 + lr;
            cp16(aB + s * A_ST + SWZ128((unsigned)(row * BKB + lc)),
                 zrow + (size_t)row * C_DIM + kb + lc);
            cp16(bB + s * B_ST + SWZ128((unsigned)(row * BKB + lc)),
                 wrow + (size_t)row * C_DIM + kb + lc);
        }
        asm volatile("cp.async.commit_group;");
    }

    for (int i = 0; i < NITER; i++) {
        asm volatile("cp.async.wait_group %0;" :: "n"(STAGES - 2));
        __syncthreads();

        if (i + STAGES - 1 < NITER) {
            int s = (i + STAGES - 1) % STAGES;
            int kb = (i + STAGES - 1) * BKB;
#pragma unroll
            for (int r = 0; r < 4; r++) {
                int row = r * 32 + lr;
                cp16(aB + s * A_ST + SWZ128((unsigned)(row * BKB + lc)),
                     zrow + (size_t)row * C_DIM + kb + lc);
                cp16(bB + s * B_ST + SWZ128((unsigned)(row * BKB + lc)),
                     wrow + (size_t)row * C_DIM + kb + lc);
            }
        }
        asm volatile("cp.async.commit_group;");

        const unsigned aS = aB + (i % STAGES) * A_ST;
        const unsigned bS = bB + (i % STAGES) * B_ST;
        const int lrow = lane & 15;
        const int lhalf = (lane >> 4) * 16;

#pragma unroll
        for (int kk = 0; kk < 4; kk++) {
            const int kbyte = kk * 32;
            unsigned af[2][4];
#pragma unroll
            for (int mt = 0; mt < 2; mt++) {
                int row = wm * 32 + mt * 16 + lrow;
                ldm4(af[mt], aS + SWZ128((unsigned)(row * BKB + kbyte + lhalf)));
            }
            unsigned bf[4][4];
#pragma unroll
            for (int nt2 = 0; nt2 < 4; nt2++) {
                int row = wn * 64 + nt2 * 16 + lrow;
                ldm4(bf[nt2], bS + SWZ128((unsigned)(row * BKB + kbyte + lhalf)));
            }
#pragma unroll
            for (int mt = 0; mt < 2; mt++)
#pragma unroll
                for (int nt = 0; nt < 8; nt++) {
                    const unsigned* bv = bf[nt >> 1];
                    unsigned b0 = (nt & 1) ? bv[1] : bv[0];
                    unsigned b1 = (nt & 1) ? bv[3] : bv[2];
                    mma_s8(acc[mt][nt], af[mt], b0, b1);
                }
        }
    }

    const int r0 = blockIdx.x * BM + wm * 32 + (lane >> 2);
    const int c0 = blockIdx.y * BN + wn * 64 + (lane & 3) * 2;
#pragma unroll
    for (int mt = 0; mt < 2; mt++) {
#pragma unroll
        for (int nt = 0; nt < 8; nt++) {
            const int c = c0 + nt * 8;
            float wh0 = g_whalf[c];
            float wh1 = g_whalf[c + 1];
            __half* p = scores + (size_t)(r0 + mt * 16) * K_DIM + c;
            *(__half2*)p = __floats2half2_rn(
                (float)acc[mt][nt][0] * QINV2 - wh0 + SHIFT,
                (float)acc[mt][nt][1] * QINV2 - wh1 + SHIFT);
            *(__half2*)(p + 8 * K_DIM) = __floats2half2_rn(
                (float)acc[mt][nt][2] * QINV2 - wh0 + SHIFT,
                (float)acc[mt][nt][3] * QINV2 - wh1 + SHIFT);
        }
    }
}

// ---------------- scan: index-free max + candidate collection ----------------
#define MARGIN 7.0f

__global__ __launch_bounds__(256) void scan_k()
{
    const int b = blockIdx.x;
    const int t = threadIdx.x;
    const int lane = t & 31;
    const int wp = t >> 5;

    __shared__ float s_wv[8];
    __shared__ float s_best;
    __shared__ int   s_besti;
    __shared__ int   s_cnt;
    __shared__ int   s_base;
    __shared__ int   s_cand[MAXC];

    uint2 raw = ((const uint2*)(g_scores + (size_t)b * K_DIM))[t];
    __half2 p0 = *(__half2*)&raw.x;
    __half2 p1 = *(__half2*)&raw.y;

    __half2 m2 = __hmax2(p0, p1);
    float2 mf = __half22float2(m2);
    float mv = fmaxf(mf.x, mf.y);
    for (int o = 16; o > 0; o >>= 1)
        mv = fmaxf(mv, __shfl_down_sync(0xFFFFFFFFu, mv, o));
    if (lane == 0) s_wv[wp] = mv;
    if (t == 0) { s_cnt = 0; s_besti = K_DIM; }
    __syncthreads();
    if (t == 0) {
        float gb = s_wv[0];
        for (int i2 = 1; i2 < 8; i2++) gb = fmaxf(gb, s_wv[i2]);
        s_best = gb;
    }
    __syncthreads();
    const float best = s_best;
    const float th = best - MARGIN;

    float2 a = __half22float2(p0);
    float2 c = __half22float2(p1);
    float v[4] = { a.x, a.y, c.x, c.y };
#pragma unroll
    for (int j = 0; j < 4; j++) {
        if (v[j] >= th) {
            int p = atomicAdd(&s_cnt, 1);
            if (p < MAXC) s_cand[p] = 4 * t + j;
            if (v[j] == best) atomicMin(&s_besti, 4 * t + j);
        }
    }
    __syncthreads();
    int cnt = s_cnt < MAXC ? s_cnt : MAXC;
    if (t == 0) {
        g_ind[b] = s_besti;
        g_bestsc[b] = best;
        if (cnt > 1) {
            g_flag[b] = 1;
            g_best[b] = 0ULL;
            s_base = atomicAdd(&g_npairs, cnt);
        } else {
            g_flag[b] = 0;
        }
    }
    __syncthreads();
    if (cnt > 1 && t < cnt)
        g_pairs[s_base + t] = (b << 10) | s_cand[t];
}

// ---------------- refine: one warp per pair (8192 warps), exact fp32 dot ----------------
__global__ __launch_bounds__(128) void refine_k(const float* __restrict__ z,
                                                const float* __restrict__ w)
{
    const int lane = threadIdx.x & 31;
    const int wp = threadIdx.x >> 5;
    const int npairs = g_npairs;

    for (int pi = blockIdx.x * 4 + wp; pi < npairs; pi += gridDim.x * 4) {
        const int pk = g_pairs[pi];
        const int b = pk >> 10;
        const int k = pk & 1023;

        const float4* zr4 = (const float4*)(z + (size_t)b * C_DIM);
        const float4* wr4 = (const float4*)(w + (size_t)k * C_DIM);
        float p = 0.0f;
#pragma unroll
        for (int d = 0; d < 16; d++) {
            float4 zv = zr4[lane + d * 32];
            float4 wv = wr4[lane + d * 32];
            p += zv.x * wv.x + zv.y * wv.y + zv.z * wv.z + zv.w * wv.w;
        }
        for (int o = 16; o > 0; o >>= 1) p += __shfl_down_sync(0xFFFFFFFFu, p, o);
        if (lane == 0) {
            float score = p - g_whalf[k];
            unsigned ub = __float_as_uint(score);
            ub = (ub & 0x80000000u) ? ~ub : (ub | 0x80000000u);
            unsigned long long packed = ((unsigned long long)ub << 32) | (unsigned)(~(unsigned)k);
            atomicMax(&g_best[b], packed);
        }
    }
}

// ---------------- gather: out = w[ind]; loss rl = znorm - 2*score_true ----------------
__global__ __launch_bounds__(256) void gather_k(const float* __restrict__ w,
                                                float* __restrict__ out)
{
    const int b = blockIdx.x;
    const int t = threadIdx.x;

    __shared__ int s_ind;
    if (t == 0) {
        int ind;
        float score_true;
        if (g_flag[b]) {
            unsigned long long pb = g_best[b];
            ind = (int)(~(unsigned)(pb & 0xFFFFFFFFu));
            unsigned ub = (unsigned)(pb >> 32);
            score_true = (ub & 0x80000000u) ? __uint_as_float(ub ^ 0x80000000u)
                                            : __uint_as_float(~ub);
        } else {
            ind = g_ind[b];
            score_true = g_bestsc[b] - SHIFT;
        }
        s_ind = ind;
        atomicAdd(&g_loss, g_znorm[b] - 2.0f * score_true);
    }
    __syncthreads();
    const int ind = s_ind;

    const float4* wr = (const float4*)(w + (size_t)ind * C_DIM);
    float4* o4 = (float4*)(out + (size_t)b * C_DIM);
#pragma unroll
    for (int c = t; c < C_DIM / 4; c += 256) {
        float4 wv = __ldg(&wr[c]);
        asm volatile("st.global.cs.v4.f32 [%0], {%1,%2,%3,%4};"
            :: "l"(o4 + c), "f"(wv.x), "f"(wv.y), "f"(wv.z), "f"(wv.w));
    }
}

__global__ void fin_k(float* out, int loss_idx, float inv_n) {
    out[loss_idx] = 12.5f * g_loss * inv_n;   // KLD_SCALE*(1+COMMITMENT_COST)*mse
}

extern "C" void kernel_launch(void* const* d_in, const int* in_sizes, int n_in,
                              void* d_out, int out_size)
{
    const float* z = (const float*)d_in[0];
    const float* w = (const float*)d_in[1];
    float* out = (float*)d_out;
    const int B = in_sizes[0] / C_DIM;   // 8192

    void* p_zb; cudaGetSymbolAddress(&p_zb, g_zb);
    void* p_wb; cudaGetSymbolAddress(&p_wb, g_wb);
    void* p_sc; cudaGetSymbolAddress(&p_sc, g_scores);

    cudaFuncSetAttribute(gemm_k, cudaFuncAttributeMaxDynamicSharedMemorySize, GSMEM);

    prep_k<<<K_DIM + B, 256>>>(z, w, (signed char*)p_zb, (signed char*)p_wb);

    dim3 ggrid(B / BM, K_DIM / BN);
    gemm_k<<<ggrid, 256, GSMEM>>>((const signed char*)p_zb,
                                  (const signed char*)p_wb,
                                  (__half*)p_sc);

    scan_k<<<B, 256>>>();
    refine_k<<<2048, 128>>>(z, w);
    gather_k<<<B, 256>>>(w, out);
    fin_k<<<1, 1>>>(out, out_size - 1, 1.0f / ((float)B * (float)C_DIM));
}